// round 10
// baseline (speedup 1.0000x reference)
#include <cuda_runtime.h>
#include <cuda_fp16.h>
#include <math.h>
#include <stdint.h>

#define Bn 8
#define Nn 8192
#define Cn 256
#define Hn 4
#define Dn 64
#define BHn (Bn*Hn)
#define MTOT (Bn*Nn)
#define GSP 16
#define GSL (Nn/GSP)
#define NCTA (MTOT/128)   // 512

// ---------------------------------------------------------------------------
// Scratch (__device__ globals; no allocation allowed)
// ---------------------------------------------------------------------------
__device__ __half g_qh [MTOT*Cn];
__device__ __half g_kh [MTOT*Cn];
__device__ __half g_wh [2*Cn*Cn];
__device__ __half g_w2h[Bn*Cn*Cn];
__device__ float  g_u  [Bn*Cn*Cn];
__device__ float  g_gp [BHn*GSP*Dn*Dn];
__device__ float  g_nssp[2*NCTA*Cn];

// ---------------------------------------------------------------------------
// Helpers
// ---------------------------------------------------------------------------
__device__ __forceinline__ uint32_t smem_u32(const void* p) {
    uint32_t a;
    asm("{ .reg .u64 t; cvta.to.shared.u64 t, %1; cvt.u32.u64 %0, t; }" : "=r"(a) : "l"(p));
    return a;
}
__device__ __forceinline__ void cp16(uint32_t sdst, const void* gsrc) {
    asm volatile("cp.async.cg.shared.global [%0], [%1], 16;"
                 :: "r"(sdst), "l"(__cvta_generic_to_global(gsrc)) : "memory");
}
#define CP_COMMIT() asm volatile("cp.async.commit_group;" ::: "memory")
#define CP_WAIT1()  asm volatile("cp.async.wait_group 1;" ::: "memory")
#define CP_WAIT2()  asm volatile("cp.async.wait_group 2;" ::: "memory")

#define LDSM4(r0, r1, r2, r3, addr) \
    asm volatile("ldmatrix.sync.aligned.m8n8.x4.shared.b16 {%0,%1,%2,%3}, [%4];" \
                 : "=r"(r0), "=r"(r1), "=r"(r2), "=r"(r3) : "r"(addr))
#define LDSM4T(r0, r1, r2, r3, addr) \
    asm volatile("ldmatrix.sync.aligned.m8n8.x4.trans.shared.b16 {%0,%1,%2,%3}, [%4];" \
                 : "=r"(r0), "=r"(r1), "=r"(r2), "=r"(r3) : "r"(addr))
#define LDSM2T(r0, r1, addr) \
    asm volatile("ldmatrix.sync.aligned.m8n8.x2.trans.shared.b16 {%0,%1}, [%2];" \
                 : "=r"(r0), "=r"(r1) : "r"(addr))

__device__ __forceinline__ void mma_f16(float* d, const uint32_t* a, const uint32_t* b) {
    asm volatile(
        "mma.sync.aligned.m16n8k16.row.col.f32.f16.f16.f32 "
        "{%0,%1,%2,%3}, {%4,%5,%6,%7}, {%8,%9}, {%0,%1,%2,%3};"
        : "+f"(d[0]), "+f"(d[1]), "+f"(d[2]), "+f"(d[3])
        : "r"(a[0]), "r"(a[1]), "r"(a[2]), "r"(a[3]), "r"(b[0]), "r"(b[1]));
}

// ---------------------------------------------------------------------------
// fp16 mma GEMM, fp32 A converted in-flight, CTA 128x256, 512 threads,
// warps 4Mx4N (32x64 each). K=256 in 4 chunks of 64, 3-stage pipeline.
// cp.async loadB issued right after the barrier (overlaps MMA region).
// ---------------------------------------------------------------------------
#define RSH 72
#define A_STG (128*RSH*2)               // 18432 B
#define B_STG (256*RSH*2)               // 36864 B
#define NST 3
#define SMEM_T (NST*(A_STG+B_STG) + 4096)

template<bool OUTF32>
__global__ void __launch_bounds__(512, 1) gemm_h(const float* __restrict__ X0,
                                                 const __half* __restrict__ W0,
                                                 __half* __restrict__ Yh0,
                                                 const float* __restrict__ X1,
                                                 const __half* __restrict__ W1,
                                                 __half* __restrict__ Yh1,
                                                 const float* __restrict__ bias,
                                                 float* __restrict__ Yf,
                                                 float* __restrict__ nssp)
{
    extern __shared__ char sm[];
    const uint32_t sA = smem_u32(sm);
    const uint32_t sB = sA + NST * A_STG;
    float* part = reinterpret_cast<float*>(sm + NST * (A_STG + B_STG));

    const int tid  = threadIdx.x;
    const int wid  = tid >> 5, lane = tid & 31;
    const int wm   = wid & 3;
    const int wn   = wid >> 2;
    const int gid  = lane >> 2;
    const int tig  = lane & 3;
    const int m0   = blockIdx.x * 128;
    const int z    = OUTF32 ? 0 : blockIdx.z;

    const float* X = (!OUTF32 && z) ? X1 : X0;
    const __half* Wp = OUTF32 ? W0 + ((size_t)(m0 >> 13) << 16) : (z ? W1 : W0);
    __half* Yh = z ? Yh1 : Yh0;

    const int lrA = ((lane >> 3) & 1) * 8 + (lane & 7);
    const int lkA = (lane >> 4) * 8;
    const int lrB = (lane >> 4) * 8 + (lane & 7);
    const int lkB = ((lane >> 3) & 1) * 8;
    int aoffs[2], boffs[4];
    #pragma unroll
    for (int mt = 0; mt < 2; mt++) aoffs[mt] = (wm * 32 + mt * 16 + lrA) * RSH + lkA;
    #pragma unroll
    for (int nb = 0; nb < 4; nb++) boffs[nb] = (wn * 64 + nb * 16 + lrB) * RSH + lkB;

    auto ldA4 = [&](int k0, float4* p) {
        #pragma unroll
        for (int i = 0; i < 4; i++) {
            int g = tid + i * 512;
            p[i] = *reinterpret_cast<const float4*>(
                X + (size_t)(m0 + (g >> 4)) * Cn + k0 + (g & 15) * 4);
        }
    };
    auto stA4 = [&](int st, const float4* p) {
        #pragma unroll
        for (int i = 0; i < 4; i++) {
            int g = tid + i * 512;
            __half2 h0 = __floats2half2_rn(p[i].x, p[i].y);
            __half2 h1 = __floats2half2_rn(p[i].z, p[i].w);
            uint2 u;
            u.x = *reinterpret_cast<uint32_t*>(&h0);
            u.y = *reinterpret_cast<uint32_t*>(&h1);
            *reinterpret_cast<uint2*>(sm + st * A_STG + ((g >> 4) * RSH + (g & 15) * 4) * 2) = u;
        }
    };
    auto loadB = [&](int st, int k0) {
        #pragma unroll
        for (int i = 0; i < 4; i++) {
            int g = tid + i * 512;
            int r = g >> 3, kq = g & 7;
            cp16(sB + st * B_STG + (r * RSH + kq * 8) * 2,
                 Wp + (size_t)r * Cn + k0 + kq * 8);
        }
    };

    float acc[2][8][4] = {};

    {   // prologue: stages 0,1
        float4 p0[4], p1[4];
        ldA4(0, p0); ldA4(64, p1);
        stA4(0, p0); loadB(0, 0);  CP_COMMIT();
        stA4(1, p1); loadB(1, 64); CP_COMMIT();
    }

    for (int ch = 0; ch < 4; ch++) {
        float4 pn[4];
        if (ch + 2 < 4) ldA4((ch + 2) * 64, pn);
        CP_WAIT1();
        __syncthreads();
        if (ch + 2 < 4) loadB((ch + 2) % 3, (ch + 2) * 64);
        CP_COMMIT();

        const int st = ch % 3;
        const uint32_t a0 = sA + st * A_STG;
        const uint32_t b0a = sB + st * B_STG;

        #pragma unroll
        for (int ks = 0; ks < 4; ks++) {
            uint32_t af[2][4];
            #pragma unroll
            for (int mt = 0; mt < 2; mt++)
                LDSM4(af[mt][0], af[mt][1], af[mt][2], af[mt][3],
                      a0 + (aoffs[mt] + ks * 16) * 2);
            uint32_t bf[8][2];
            #pragma unroll
            for (int nb = 0; nb < 4; nb++) {
                uint32_t r0, r1, r2, r3;
                LDSM4(r0, r1, r2, r3, b0a + (boffs[nb] + ks * 16) * 2);
                bf[nb * 2][0] = r0; bf[nb * 2][1] = r1;
                bf[nb * 2 + 1][0] = r2; bf[nb * 2 + 1][1] = r3;
            }
            #pragma unroll
            for (int mt = 0; mt < 2; mt++)
                #pragma unroll
                for (int nt = 0; nt < 8; nt++)
                    mma_f16(acc[mt][nt], af[mt], bf[nt]);
        }

        if (ch + 2 < 4) stA4((ch + 2) % 3, pn);
    }

    // Output
    #pragma unroll
    for (int mt = 0; mt < 2; mt++) {
        const int m = m0 + wm * 32 + mt * 16 + gid;
        #pragma unroll
        for (int nt = 0; nt < 8; nt++) {
            const int cg = wn * 64 + nt * 8 + tig * 2;
            if (OUTF32) {
                float b0 = __ldg(bias + cg), b1 = __ldg(bias + cg + 1);
                float2 v0 = make_float2(acc[mt][nt][0] + b0, acc[mt][nt][1] + b1);
                float2 v1 = make_float2(acc[mt][nt][2] + b0, acc[mt][nt][3] + b1);
                *reinterpret_cast<float2*>(Yf + (size_t)m * Cn + cg)       = v0;
                *reinterpret_cast<float2*>(Yf + (size_t)(m + 8) * Cn + cg) = v1;
            } else {
                __half2 h0 = __floats2half2_rn(acc[mt][nt][0], acc[mt][nt][1]);
                __half2 h1 = __floats2half2_rn(acc[mt][nt][2], acc[mt][nt][3]);
                *reinterpret_cast<__half2*>(Yh + (size_t)m * Cn + cg)       = h0;
                *reinterpret_cast<__half2*>(Yh + (size_t)(m + 8) * Cn + cg) = h1;
            }
        }
    }

    if (!OUTF32) {
        float cs[8][2];
        #pragma unroll
        for (int nt = 0; nt < 8; nt++) {
            cs[nt][0] = acc[0][nt][0] * acc[0][nt][0] + acc[0][nt][2] * acc[0][nt][2]
                      + acc[1][nt][0] * acc[1][nt][0] + acc[1][nt][2] * acc[1][nt][2];
            cs[nt][1] = acc[0][nt][1] * acc[0][nt][1] + acc[0][nt][3] * acc[0][nt][3]
                      + acc[1][nt][1] * acc[1][nt][1] + acc[1][nt][3] * acc[1][nt][3];
        }
        #pragma unroll
        for (int nt = 0; nt < 8; nt++)
            #pragma unroll
            for (int j = 0; j < 2; j++) {
                cs[nt][j] += __shfl_xor_sync(0xffffffffu, cs[nt][j], 4);
                cs[nt][j] += __shfl_xor_sync(0xffffffffu, cs[nt][j], 8);
                cs[nt][j] += __shfl_xor_sync(0xffffffffu, cs[nt][j], 16);
            }
        if (gid == 0) {
            #pragma unroll
            for (int nt = 0; nt < 8; nt++) {
                part[wm * 256 + wn * 64 + nt * 8 + tig * 2]     = cs[nt][0];
                part[wm * 256 + wn * 64 + nt * 8 + tig * 2 + 1] = cs[nt][1];
            }
        }
        __syncthreads();
        if (tid < 256) {
            float s = part[tid] + part[256 + tid] + part[512 + tid] + part[768 + tid];
            nssp[((size_t)z * NCTA + blockIdx.x) * 256 + tid] = s;
        }
    }
}

// ---------------------------------------------------------------------------
// Gram via fp16 mma with ldmatrix.trans — 4-stage cp.async, single barrier
// ---------------------------------------------------------------------------
#define GRS 72
#define GSTG (64*GRS*2)          // 9216 B per operand per stage
#define GSMEM (8*GSTG)           // 73728 B

__global__ void __launch_bounds__(256) gram_mma(const __half* __restrict__ Qh,
                                                const __half* __restrict__ Kh,
                                                float* __restrict__ Gp)
{
    extern __shared__ char smg[];
    const uint32_t sq = smem_u32(smg);
    const uint32_t sk = sq + 4 * GSTG;

    const int bh = blockIdx.x, sp = blockIdx.y;
    const int b = bh >> 2, h = bh & 3;
    const int tid = threadIdx.x;
    const int w = tid >> 5, lane = tid & 31;
    const int gid = lane >> 2, tig = lane & 3;
    const int t0 = sp * GSL;

    const __half* qb = Qh + ((size_t)b * Nn) * 256 + h * 64;
    const __half* kb = Kh + ((size_t)b * Nn) * 256 + h * 64;

    auto gload = [&](int st, int tc) {
        #pragma unroll
        for (int i = 0; i < 2; i++) {
            int g = tid + i * 256;
            int r = g >> 3, ck = g & 7;
            cp16(sq + st * GSTG + (r * GRS + ck * 8) * 2,
                 qb + (size_t)(t0 + tc + r) * 256 + ck * 8);
        }
        #pragma unroll
        for (int i = 0; i < 2; i++) {
            int g = tid + i * 256;
            int r = g >> 3, ck = g & 7;
            cp16(sk + st * GSTG + (r * GRS + ck * 8) * 2,
                 kb + (size_t)(t0 + tc + r) * 256 + ck * 8);
        }
    };

    const int aH = (((lane >> 4) & 1) * 8 + (lane & 7)) * GRS + ((lane >> 3) & 1) * 8;
    const int bH = (((lane >> 3) & 1) * 8 + (lane & 7)) * GRS + w * 8;

    float acc[4][4] = {};

    gload(0, 0);   CP_COMMIT();
    gload(1, 64);  CP_COMMIT();
    gload(2, 128); CP_COMMIT();

    const int NCH = GSL / 64;   // 8
    for (int c = 0; c < NCH; c++) {
        CP_WAIT2();
        __syncthreads();
        if (c + 3 < NCH) gload((c + 3) & 3, (c + 3) * 64);
        CP_COMMIT();

        const uint32_t aq = sq + (c & 3) * GSTG;
        const uint32_t ak = sk + (c & 3) * GSTG;

        #pragma unroll
        for (int st16 = 0; st16 < 4; st16++) {
            const int kb16 = st16 * 16;
            uint32_t bfr[2];
            LDSM2T(bfr[0], bfr[1], ak + (kb16 * GRS + bH) * 2);
            #pragma unroll
            for (int mt = 0; mt < 4; mt++) {
                uint32_t af[4];
                LDSM4T(af[0], af[1], af[2], af[3],
                       aq + (kb16 * GRS + aH + mt * 16) * 2);
                mma_f16(acc[mt], af, bfr);
            }
        }
    }

    float* g = Gp + (((size_t)bh * GSP + sp) << 12);
    #pragma unroll
    for (int mt = 0; mt < 4; mt++) {
        const int r0 = mt * 16 + gid;
        *reinterpret_cast<float2*>(g + r0 * 64 + w * 8 + tig * 2) =
            make_float2(acc[mt][0], acc[mt][1]);
        *reinterpret_cast<float2*>(g + (r0 + 8) * 64 + w * 8 + tig * 2) =
            make_float2(acc[mt][2], acc[mt][3]);
    }
}

// ---------------------------------------------------------------------------
// Weight f32 -> f16
// ---------------------------------------------------------------------------
__device__ __forceinline__ void cvt_store4(__half* dst, float4 v) {
    __half2 h0 = __floats2half2_rn(v.x, v.y);
    __half2 h1 = __floats2half2_rn(v.z, v.w);
    uint2 u;
    u.x = *reinterpret_cast<uint32_t*>(&h0);
    u.y = *reinterpret_cast<uint32_t*>(&h1);
    *reinterpret_cast<uint2*>(dst) = u;
}

__global__ void __launch_bounds__(256) cvt_w_kernel(const float4* __restrict__ wq,
                                                    const float4* __restrict__ wk,
                                                    __half* dst)
{
    const int n4 = (Cn * Cn) / 4;
    const float4* src = blockIdx.y == 0 ? wq : wk;
    __half* d = dst + (size_t)blockIdx.y * Cn * Cn;
    int i = blockIdx.x * 256 + threadIdx.x;
    if (i < n4) cvt_store4(d + i * 4, src[i]);
}

// ---------------------------------------------------------------------------
// Fused: norm reduce + gram reduce + softmax + fold1 (one block per bh)
// U_b[h*64+dd][k] = sum_e attn[bh][dd][e] * Wv[h*64+e][k]
// ---------------------------------------------------------------------------
__global__ void __launch_bounds__(256) attn_fold1(const float* __restrict__ Gp,
                                                  const float* __restrict__ nssp,
                                                  const float* __restrict__ temp,
                                                  const float* __restrict__ Wv,
                                                  float* __restrict__ U)
{
    __shared__ float at[64][65];
    __shared__ float wvs[64][65];
    __shared__ float red4[4][64];
    __shared__ float srq[64];
    __shared__ float srk[64];

    const int bh = blockIdx.x, b = bh >> 2, h = bh & 3;
    const int t = threadIdx.x;
    const int dc = t & 63, grp = t >> 6;

    // q norms (64 CTA partials per batch, fixed order)
    float s = 0.f;
    #pragma unroll 4
    for (int i = 0; i < 16; i++)
        s += nssp[((size_t)0 * NCTA + b * 64 + grp * 16 + i) * 256 + h * 64 + dc];
    red4[grp][dc] = s;
    __syncthreads();
    if (t < 64)
        srq[t] = 1.0f / fmaxf(sqrtf(red4[0][t] + red4[1][t] + red4[2][t] + red4[3][t]), 1e-12f);
    __syncthreads();
    // k norms
    s = 0.f;
    #pragma unroll 4
    for (int i = 0; i < 16; i++)
        s += nssp[((size_t)1 * NCTA + b * 64 + grp * 16 + i) * 256 + h * 64 + dc];
    red4[grp][dc] = s;
    __syncthreads();
    if (t < 64)
        srk[t] = 1.0f / fmaxf(sqrtf(red4[0][t] + red4[1][t] + red4[2][t] + red4[3][t]), 1e-12f);
    __syncthreads();

    const float tp = temp[h];

    // gram split-K reduce + rank-1 scale
    #pragma unroll
    for (int i = 0; i < 16; i++) {
        int idx = t + i * 256;
        int d2 = idx >> 6, e2 = idx & 63;
        float g = 0.f;
        #pragma unroll
        for (int sp = 0; sp < GSP; sp++)
            g += Gp[(((size_t)bh * GSP + sp) << 12) + idx];
        at[d2][e2] = g * srq[d2] * srk[e2] * tp;
    }
    __syncthreads();

    // softmax: row r = t>>2, 4 threads per row, 16 e each
    {
        const int r = t >> 2, seg = (t & 3) * 16;
        float ex[16];
        float m = -1e30f;
        #pragma unroll
        for (int e = 0; e < 16; e++) m = fmaxf(m, at[r][seg + e]);
        m = fmaxf(m, __shfl_xor_sync(0xffffffffu, m, 1));
        m = fmaxf(m, __shfl_xor_sync(0xffffffffu, m, 2));
        float ssum = 0.f;
        #pragma unroll
        for (int e = 0; e < 16; e++) { ex[e] = __expf(at[r][seg + e] - m); ssum += ex[e]; }
        ssum += __shfl_xor_sync(0xffffffffu, ssum, 1);
        ssum += __shfl_xor_sync(0xffffffffu, ssum, 2);
        const float inv = 1.0f / ssum;
        #pragma unroll
        for (int e = 0; e < 16; e++) at[r][seg + e] = ex[e] * inv;
    }
    __syncthreads();

    // fold1: U rows for this bh, 64x256 in 4 column blocks of 64
    const int tx = t & 15, ty = t >> 4;
    for (int kq = 0; kq < 4; kq++) {
        #pragma unroll
        for (int i = 0; i < 16; i++) {
            int idx = t + i * 256;   // e*64 + j
            wvs[idx >> 6][idx & 63] =
                Wv[(size_t)(h * 64 + (idx >> 6)) * 256 + kq * 64 + (idx & 63)];
        }
        __syncthreads();
        float acc[4][4] = {};
        #pragma unroll
        for (int e = 0; e < 64; e++) {
            float av[4], bv[4];
            #pragma unroll
            for (int i = 0; i < 4; i++) av[i] = at[ty * 4 + i][e];
            #pragma unroll
            for (int j = 0; j < 4; j++) bv[j] = wvs[e][tx * 4 + j];
            #pragma unroll
            for (int i = 0; i < 4; i++)
                #pragma unroll
                for (int j = 0; j < 4; j++)
                    acc[i][j] += av[i] * bv[j];
        }
        #pragma unroll
        for (int i = 0; i < 4; i++)
            #pragma unroll
            for (int j = 0; j < 4; j++)
                U[((size_t)b * 256 + h * 64 + ty * 4 + i) * 256 + kq * 64 + tx * 4 + j] =
                    acc[i][j];
        __syncthreads();
    }
}

// ---------------------------------------------------------------------------
// fold2: W2_b[c][k] = sum_ddg Wo[c][ddg] * U_b[ddg][k]   -> fp16
// ---------------------------------------------------------------------------
__global__ void __launch_bounds__(256) fold2_kernel(const float* __restrict__ Wo,
                                                    const float* __restrict__ U,
                                                    __half* __restrict__ W2)
{
    __shared__ float ws[16][68];
    __shared__ float us[16][68];
    const int cq = blockIdx.x, kq = blockIdx.y, b = blockIdx.z;
    const int tid = threadIdx.x;
    const int tx = tid & 15, ty = tid >> 4;
    const int lrow = tid >> 2, lk4 = (tid & 3) * 4;
    const int krow = tid >> 4, kc4 = (tid & 15) * 4;

    const float* Ub = U + ((size_t)b << 16);
    float acc[4][4] = {};

    for (int k0 = 0; k0 < 256; k0 += 16) {
        float4 wv4 = *reinterpret_cast<const float4*>(
            Wo + (size_t)(cq * 64 + lrow) * 256 + k0 + lk4);
        float4 uv4 = *reinterpret_cast<const float4*>(
            Ub + (size_t)(k0 + krow) * 256 + kq * 64 + kc4);
        __syncthreads();
        ws[lk4+0][lrow] = wv4.x; ws[lk4+1][lrow] = wv4.y;
        ws[lk4+2][lrow] = wv4.z; ws[lk4+3][lrow] = wv4.w;
        *reinterpret_cast<float4*>(&us[krow][kc4]) = uv4;
        __syncthreads();
        #pragma unroll
        for (int kk = 0; kk < 16; kk++) {
            float4 a = *reinterpret_cast<const float4*>(&ws[kk][ty * 4]);
            float4 bb = *reinterpret_cast<const float4*>(&us[kk][tx * 4]);
            float av[4] = {a.x, a.y, a.z, a.w};
            float bv[4] = {bb.x, bb.y, bb.z, bb.w};
            #pragma unroll
            for (int i = 0; i < 4; i++)
                #pragma unroll
                for (int j = 0; j < 4; j++)
                    acc[i][j] += av[i] * bv[j];
        }
    }
    #pragma unroll
    for (int i = 0; i < 4; i++)
        #pragma unroll
        for (int j = 0; j < 4; j++)
            W2[((size_t)b << 16) + (size_t)(cq * 64 + ty * 4 + i) * 256 + kq * 64 + tx * 4 + j] =
                __float2half(acc[i][j]);
}

// ---------------------------------------------------------------------------
extern "C" void kernel_launch(void* const* d_in, const int* in_sizes, int n_in,
                              void* d_out, int out_size)
{
    (void)in_sizes; (void)n_in; (void)out_size;
    const float* x1 = (const float*)d_in[0];
    const float* x2 = (const float*)d_in[1];
    const float* Wq = (const float*)d_in[2];
    const float* Wk = (const float*)d_in[3];
    const float* Wv = (const float*)d_in[4];
    const float* Wo = (const float*)d_in[5];
    const float* bo = (const float*)d_in[6];
    const float* temperature = (const float*)d_in[7];
    float* out = (float*)d_out;

    __half *qh, *kh, *wh, *w2h;
    float *u, *gp, *nssp;
    cudaGetSymbolAddress((void**)&qh,  g_qh);
    cudaGetSymbolAddress((void**)&kh,  g_kh);
    cudaGetSymbolAddress((void**)&wh,  g_wh);
    cudaGetSymbolAddress((void**)&w2h, g_w2h);
    cudaGetSymbolAddress((void**)&u,   g_u);
    cudaGetSymbolAddress((void**)&gp,  g_gp);
    cudaGetSymbolAddress((void**)&nssp, g_nssp);

    cudaFuncSetAttribute(gemm_h<false>, cudaFuncAttributeMaxDynamicSharedMemorySize, SMEM_T);
    cudaFuncSetAttribute(gemm_h<true >, cudaFuncAttributeMaxDynamicSharedMemorySize, SMEM_T);
    cudaFuncSetAttribute(gram_mma, cudaFuncAttributeMaxDynamicSharedMemorySize, GSMEM);

    cvt_w_kernel<<<dim3(64, 2), 256>>>((const float4*)Wq, (const float4*)Wk, wh);

    gemm_h<false><<<dim3(NCTA, 1, 2), 512, SMEM_T>>>(
        x1, wh, qh, x2, wh + Cn * Cn, kh, nullptr, nullptr, nssp);

    gram_mma<<<dim3(BHn, GSP), 256, GSMEM>>>(qh, kh, gp);
    attn_fold1<<<BHn, 256>>>(gp, nssp, temperature, Wv, u);
    fold2_kernel<<<dim3(4, 4, Bn), 256>>>(Wo, u, w2h);

    gemm_h<true><<<dim3(NCTA, 1, 1), 512, SMEM_T>>>(
        x2, w2h, nullptr, nullptr, nullptr, nullptr, bo, out, nullptr);
}

// round 11
// speedup vs baseline: 1.0415x; 1.0415x over previous
#include <cuda_runtime.h>
#include <cuda_fp16.h>
#include <math.h>
#include <stdint.h>

#define Bn 8
#define Nn 8192
#define Cn 256
#define Hn 4
#define Dn 64
#define BHn (Bn*Hn)
#define MTOT (Bn*Nn)
#define GSP 16
#define GSL (Nn/GSP)
#define NCTA (MTOT/128)   // 512

// ---------------------------------------------------------------------------
// Scratch (__device__ globals; no allocation allowed)
// ---------------------------------------------------------------------------
__device__ __half g_qh [MTOT*Cn];
__device__ __half g_kh [MTOT*Cn];
__device__ __half g_wh [2*Cn*Cn];
__device__ __half g_w2h[Bn*Cn*Cn];
__device__ float  g_u  [Bn*Cn*Cn];
__device__ float  g_gp [BHn*GSP*Dn*Dn];
__device__ float  g_attn[BHn*Dn*Dn];
__device__ float  g_nssp[2*NCTA*Cn];
__device__ float  g_nss2[2*Bn*Cn];

// ---------------------------------------------------------------------------
// Helpers
// ---------------------------------------------------------------------------
__device__ __forceinline__ uint32_t smem_u32(const void* p) {
    uint32_t a;
    asm("{ .reg .u64 t; cvta.to.shared.u64 t, %1; cvt.u32.u64 %0, t; }" : "=r"(a) : "l"(p));
    return a;
}
__device__ __forceinline__ void cp16(uint32_t sdst, const void* gsrc) {
    asm volatile("cp.async.cg.shared.global [%0], [%1], 16;"
                 :: "r"(sdst), "l"(__cvta_generic_to_global(gsrc)) : "memory");
}
#define CP_COMMIT() asm volatile("cp.async.commit_group;" ::: "memory")
#define CP_WAIT1()  asm volatile("cp.async.wait_group 1;" ::: "memory")
#define CP_WAIT2()  asm volatile("cp.async.wait_group 2;" ::: "memory")

#define LDSM4(r0, r1, r2, r3, addr) \
    asm volatile("ldmatrix.sync.aligned.m8n8.x4.shared.b16 {%0,%1,%2,%3}, [%4];" \
                 : "=r"(r0), "=r"(r1), "=r"(r2), "=r"(r3) : "r"(addr))
#define LDSM4T(r0, r1, r2, r3, addr) \
    asm volatile("ldmatrix.sync.aligned.m8n8.x4.trans.shared.b16 {%0,%1,%2,%3}, [%4];" \
                 : "=r"(r0), "=r"(r1), "=r"(r2), "=r"(r3) : "r"(addr))
#define LDSM2T(r0, r1, addr) \
    asm volatile("ldmatrix.sync.aligned.m8n8.x2.trans.shared.b16 {%0,%1}, [%2];" \
                 : "=r"(r0), "=r"(r1) : "r"(addr))

__device__ __forceinline__ void mma_f16(float* d, const uint32_t* a, const uint32_t* b) {
    asm volatile(
        "mma.sync.aligned.m16n8k16.row.col.f32.f16.f16.f32 "
        "{%0,%1,%2,%3}, {%4,%5,%6,%7}, {%8,%9}, {%0,%1,%2,%3};"
        : "+f"(d[0]), "+f"(d[1]), "+f"(d[2]), "+f"(d[3])
        : "r"(a[0]), "r"(a[1]), "r"(a[2]), "r"(a[3]), "r"(b[0]), "r"(b[1]));
}

// ---------------------------------------------------------------------------
// fp16 mma GEMM, fp32 A converted in-flight, CTA 128x256, 512 threads,
// warps 4Mx4N (32x64 each). K=256 in 4 chunks of 64, 3-stage pipeline.
// cp.async loadB issued right after the barrier (overlaps MMA region).
// ---------------------------------------------------------------------------
#define RSH 72
#define A_STG (128*RSH*2)               // 18432 B
#define B_STG (256*RSH*2)               // 36864 B
#define NST 3
#define SMEM_T (NST*(A_STG+B_STG) + 4096)

template<bool OUTF32>
__global__ void __launch_bounds__(512, 1) gemm_h(const float* __restrict__ X0,
                                                 const __half* __restrict__ W0,
                                                 __half* __restrict__ Yh0,
                                                 const float* __restrict__ X1,
                                                 const __half* __restrict__ W1,
                                                 __half* __restrict__ Yh1,
                                                 const float* __restrict__ bias,
                                                 float* __restrict__ Yf,
                                                 float* __restrict__ nssp)
{
    extern __shared__ char sm[];
    const uint32_t sA = smem_u32(sm);
    const uint32_t sB = sA + NST * A_STG;
    float* part = reinterpret_cast<float*>(sm + NST * (A_STG + B_STG));

    const int tid  = threadIdx.x;
    const int wid  = tid >> 5, lane = tid & 31;
    const int wm   = wid & 3;
    const int wn   = wid >> 2;
    const int gid  = lane >> 2;
    const int tig  = lane & 3;
    const int m0   = blockIdx.x * 128;
    const int z    = OUTF32 ? 0 : blockIdx.z;

    const float* X = (!OUTF32 && z) ? X1 : X0;
    const __half* Wp = OUTF32 ? W0 + ((size_t)(m0 >> 13) << 16) : (z ? W1 : W0);
    __half* Yh = z ? Yh1 : Yh0;

    const int lrA = ((lane >> 3) & 1) * 8 + (lane & 7);
    const int lkA = (lane >> 4) * 8;
    const int lrB = (lane >> 4) * 8 + (lane & 7);
    const int lkB = ((lane >> 3) & 1) * 8;
    int aoffs[2], boffs[4];
    #pragma unroll
    for (int mt = 0; mt < 2; mt++) aoffs[mt] = (wm * 32 + mt * 16 + lrA) * RSH + lkA;
    #pragma unroll
    for (int nb = 0; nb < 4; nb++) boffs[nb] = (wn * 64 + nb * 16 + lrB) * RSH + lkB;

    auto ldA4 = [&](int k0, float4* p) {
        #pragma unroll
        for (int i = 0; i < 4; i++) {
            int g = tid + i * 512;
            p[i] = *reinterpret_cast<const float4*>(
                X + (size_t)(m0 + (g >> 4)) * Cn + k0 + (g & 15) * 4);
        }
    };
    auto stA4 = [&](int st, const float4* p) {
        #pragma unroll
        for (int i = 0; i < 4; i++) {
            int g = tid + i * 512;
            __half2 h0 = __floats2half2_rn(p[i].x, p[i].y);
            __half2 h1 = __floats2half2_rn(p[i].z, p[i].w);
            uint2 u;
            u.x = *reinterpret_cast<uint32_t*>(&h0);
            u.y = *reinterpret_cast<uint32_t*>(&h1);
            *reinterpret_cast<uint2*>(sm + st * A_STG + ((g >> 4) * RSH + (g & 15) * 4) * 2) = u;
        }
    };
    auto loadB = [&](int st, int k0) {
        #pragma unroll
        for (int i = 0; i < 4; i++) {
            int g = tid + i * 512;
            int r = g >> 3, kq = g & 7;
            cp16(sB + st * B_STG + (r * RSH + kq * 8) * 2,
                 Wp + (size_t)r * Cn + k0 + kq * 8);
        }
    };

    float acc[2][8][4] = {};

    {   // prologue: stages 0,1
        float4 p0[4], p1[4];
        ldA4(0, p0); ldA4(64, p1);
        stA4(0, p0); loadB(0, 0);  CP_COMMIT();
        stA4(1, p1); loadB(1, 64); CP_COMMIT();
    }

    for (int ch = 0; ch < 4; ch++) {
        float4 pn[4];
        if (ch + 2 < 4) ldA4((ch + 2) * 64, pn);
        CP_WAIT1();
        __syncthreads();
        if (ch + 2 < 4) loadB((ch + 2) % 3, (ch + 2) * 64);
        CP_COMMIT();

        const int st = ch % 3;
        const uint32_t a0 = sA + st * A_STG;
        const uint32_t b0a = sB + st * B_STG;

        #pragma unroll
        for (int ks = 0; ks < 4; ks++) {
            uint32_t af[2][4];
            #pragma unroll
            for (int mt = 0; mt < 2; mt++)
                LDSM4(af[mt][0], af[mt][1], af[mt][2], af[mt][3],
                      a0 + (aoffs[mt] + ks * 16) * 2);
            uint32_t bf[8][2];
            #pragma unroll
            for (int nb = 0; nb < 4; nb++) {
                uint32_t r0, r1, r2, r3;
                LDSM4(r0, r1, r2, r3, b0a + (boffs[nb] + ks * 16) * 2);
                bf[nb * 2][0] = r0; bf[nb * 2][1] = r1;
                bf[nb * 2 + 1][0] = r2; bf[nb * 2 + 1][1] = r3;
            }
            #pragma unroll
            for (int mt = 0; mt < 2; mt++)
                #pragma unroll
                for (int nt = 0; nt < 8; nt++)
                    mma_f16(acc[mt][nt], af[mt], bf[nt]);
        }

        if (ch + 2 < 4) stA4((ch + 2) % 3, pn);
    }

    // Output
    #pragma unroll
    for (int mt = 0; mt < 2; mt++) {
        const int m = m0 + wm * 32 + mt * 16 + gid;
        #pragma unroll
        for (int nt = 0; nt < 8; nt++) {
            const int cg = wn * 64 + nt * 8 + tig * 2;
            if (OUTF32) {
                float b0 = __ldg(bias + cg), b1 = __ldg(bias + cg + 1);
                float2 v0 = make_float2(acc[mt][nt][0] + b0, acc[mt][nt][1] + b1);
                float2 v1 = make_float2(acc[mt][nt][2] + b0, acc[mt][nt][3] + b1);
                *reinterpret_cast<float2*>(Yf + (size_t)m * Cn + cg)       = v0;
                *reinterpret_cast<float2*>(Yf + (size_t)(m + 8) * Cn + cg) = v1;
            } else {
                __half2 h0 = __floats2half2_rn(acc[mt][nt][0], acc[mt][nt][1]);
                __half2 h1 = __floats2half2_rn(acc[mt][nt][2], acc[mt][nt][3]);
                *reinterpret_cast<__half2*>(Yh + (size_t)m * Cn + cg)       = h0;
                *reinterpret_cast<__half2*>(Yh + (size_t)(m + 8) * Cn + cg) = h1;
            }
        }
    }

    if (!OUTF32) {
        float cs[8][2];
        #pragma unroll
        for (int nt = 0; nt < 8; nt++) {
            cs[nt][0] = acc[0][nt][0] * acc[0][nt][0] + acc[0][nt][2] * acc[0][nt][2]
                      + acc[1][nt][0] * acc[1][nt][0] + acc[1][nt][2] * acc[1][nt][2];
            cs[nt][1] = acc[0][nt][1] * acc[0][nt][1] + acc[0][nt][3] * acc[0][nt][3]
                      + acc[1][nt][1] * acc[1][nt][1] + acc[1][nt][3] * acc[1][nt][3];
        }
        #pragma unroll
        for (int nt = 0; nt < 8; nt++)
            #pragma unroll
            for (int j = 0; j < 2; j++) {
                cs[nt][j] += __shfl_xor_sync(0xffffffffu, cs[nt][j], 4);
                cs[nt][j] += __shfl_xor_sync(0xffffffffu, cs[nt][j], 8);
                cs[nt][j] += __shfl_xor_sync(0xffffffffu, cs[nt][j], 16);
            }
        if (gid == 0) {
            #pragma unroll
            for (int nt = 0; nt < 8; nt++) {
                part[wm * 256 + wn * 64 + nt * 8 + tig * 2]     = cs[nt][0];
                part[wm * 256 + wn * 64 + nt * 8 + tig * 2 + 1] = cs[nt][1];
            }
        }
        __syncthreads();
        if (tid < 256) {
            float s = part[tid] + part[256 + tid] + part[512 + tid] + part[768 + tid];
            nssp[((size_t)z * NCTA + blockIdx.x) * 256 + tid] = s;
        }
    }
}

// ---------------------------------------------------------------------------
// Reduce per-CTA sumsq partials -> per-batch norms (deterministic order)
// ---------------------------------------------------------------------------
__global__ void __launch_bounds__(256) reduce_nss(const float* __restrict__ nssp,
                                                  float* __restrict__ nss2)
{
    const int b = blockIdx.x, z = blockIdx.y, c = threadIdx.x;
    float s = 0.f;
    #pragma unroll 8
    for (int i = 0; i < 64; i++)
        s += nssp[((size_t)z * NCTA + b * 64 + i) * 256 + c];
    nss2[(z * Bn + b) * 256 + c] = s;
}

// ---------------------------------------------------------------------------
// Gram via fp16 mma with ldmatrix.trans — 4-stage cp.async, single barrier
// ---------------------------------------------------------------------------
#define GRS 72
#define GSTG (64*GRS*2)          // 9216 B per operand per stage
#define GSMEM (8*GSTG)           // 73728 B

__global__ void __launch_bounds__(256) gram_mma(const __half* __restrict__ Qh,
                                                const __half* __restrict__ Kh,
                                                float* __restrict__ Gp)
{
    extern __shared__ char smg[];
    const uint32_t sq = smem_u32(smg);
    const uint32_t sk = sq + 4 * GSTG;

    const int bh = blockIdx.x, sp = blockIdx.y;
    const int b = bh >> 2, h = bh & 3;
    const int tid = threadIdx.x;
    const int w = tid >> 5, lane = tid & 31;
    const int gid = lane >> 2, tig = lane & 3;
    const int t0 = sp * GSL;

    const __half* qb = Qh + ((size_t)b * Nn) * 256 + h * 64;
    const __half* kb = Kh + ((size_t)b * Nn) * 256 + h * 64;

    auto gload = [&](int st, int tc) {
        #pragma unroll
        for (int i = 0; i < 2; i++) {
            int g = tid + i * 256;
            int r = g >> 3, ck = g & 7;
            cp16(sq + st * GSTG + (r * GRS + ck * 8) * 2,
                 qb + (size_t)(t0 + tc + r) * 256 + ck * 8);
        }
        #pragma unroll
        for (int i = 0; i < 2; i++) {
            int g = tid + i * 256;
            int r = g >> 3, ck = g & 7;
            cp16(sk + st * GSTG + (r * GRS + ck * 8) * 2,
                 kb + (size_t)(t0 + tc + r) * 256 + ck * 8);
        }
    };

    const int aH = (((lane >> 4) & 1) * 8 + (lane & 7)) * GRS + ((lane >> 3) & 1) * 8;
    const int bH = (((lane >> 3) & 1) * 8 + (lane & 7)) * GRS + w * 8;

    float acc[4][4] = {};

    gload(0, 0);   CP_COMMIT();
    gload(1, 64);  CP_COMMIT();
    gload(2, 128); CP_COMMIT();

    const int NCH = GSL / 64;   // 8
    for (int c = 0; c < NCH; c++) {
        CP_WAIT2();
        __syncthreads();
        if (c + 3 < NCH) gload((c + 3) & 3, (c + 3) * 64);
        CP_COMMIT();

        const uint32_t aq = sq + (c & 3) * GSTG;
        const uint32_t ak = sk + (c & 3) * GSTG;

        #pragma unroll
        for (int st16 = 0; st16 < 4; st16++) {
            const int kb16 = st16 * 16;
            uint32_t bfr[2];
            LDSM2T(bfr[0], bfr[1], ak + (kb16 * GRS + bH) * 2);
            #pragma unroll
            for (int mt = 0; mt < 4; mt++) {
                uint32_t af[4];
                LDSM4T(af[0], af[1], af[2], af[3],
                       aq + (kb16 * GRS + aH + mt * 16) * 2);
                mma_f16(acc[mt], af, bfr);
            }
        }
    }

    float* g = Gp + (((size_t)bh * GSP + sp) << 12);
    #pragma unroll
    for (int mt = 0; mt < 4; mt++) {
        const int r0 = mt * 16 + gid;
        *reinterpret_cast<float2*>(g + r0 * 64 + w * 8 + tig * 2) =
            make_float2(acc[mt][0], acc[mt][1]);
        *reinterpret_cast<float2*>(g + (r0 + 8) * 64 + w * 8 + tig * 2) =
            make_float2(acc[mt][2], acc[mt][3]);
    }
}

// ---------------------------------------------------------------------------
// Weight f32 -> f16
// ---------------------------------------------------------------------------
__device__ __forceinline__ void cvt_store4(__half* dst, float4 v) {
    __half2 h0 = __floats2half2_rn(v.x, v.y);
    __half2 h1 = __floats2half2_rn(v.z, v.w);
    uint2 u;
    u.x = *reinterpret_cast<uint32_t*>(&h0);
    u.y = *reinterpret_cast<uint32_t*>(&h1);
    *reinterpret_cast<uint2*>(dst) = u;
}

__global__ void __launch_bounds__(256) cvt_w_kernel(const float4* __restrict__ wq,
                                                    const float4* __restrict__ wk,
                                                    __half* dst)
{
    const int n4 = (Cn * Cn) / 4;
    const float4* src = blockIdx.y == 0 ? wq : wk;
    __half* d = dst + (size_t)blockIdx.y * Cn * Cn;
    int i = blockIdx.x * 256 + threadIdx.x;
    if (i < n4) cvt_store4(d + i * 4, src[i]);
}

// ---------------------------------------------------------------------------
// Reduce gram partials, normalize * temperature, softmax
// ---------------------------------------------------------------------------
__global__ void __launch_bounds__(64) softmax_kernel(const float* __restrict__ Gp,
                                                     const float* __restrict__ nss2,
                                                     const float* __restrict__ temp,
                                                     float* __restrict__ A)
{
    const int r  = blockIdx.x;
    const int bh = r >> 6;
    const int dd = r & 63;
    const int b  = bh >> 2, h = bh & 3;
    const int e  = threadIdx.x;

    const float rq = 1.0f / fmaxf(sqrtf(nss2[(0 * Bn + b) * 256 + h * 64 + dd]), 1e-12f);
    const float rk = 1.0f / fmaxf(sqrtf(nss2[(1 * Bn + b) * 256 + h * 64 + e]), 1e-12f);

    float s = 0.f;
    #pragma unroll
    for (int sp = 0; sp < GSP; sp++)
        s += Gp[(((size_t)bh * GSP + sp) << 12) + dd * 64 + e];
    s *= rq * rk * temp[h];

    __shared__ float red[64];
    red[e] = s;
    __syncthreads();
    for (int st = 32; st > 0; st >>= 1) {
        if (e < st) red[e] = fmaxf(red[e], red[e + st]);
        __syncthreads();
    }
    float m = red[0];
    __syncthreads();
    float ex = __expf(s - m);
    red[e] = ex;
    __syncthreads();
    for (int st = 32; st > 0; st >>= 1) {
        if (e < st) red[e] += red[e + st];
        __syncthreads();
    }
    A[(size_t)bh * 4096 + dd * 64 + e] = ex / red[0];
}

// ---------------------------------------------------------------------------
// fold1: U_b[h*64+dd][k] = sum_e attn[bh][dd][e] * Wv[h*64+e][k]   (fp32)
// ---------------------------------------------------------------------------
__global__ void __launch_bounds__(256) fold1_kernel(const float* __restrict__ A,
                                                    const float* __restrict__ Wv,
                                                    float* __restrict__ U)
{
    __shared__ float at[64][65];
    __shared__ float wv[64][65];
    const int bh = blockIdx.x, kq = blockIdx.y;
    const int b = bh >> 2, h = bh & 3;
    const int tx = threadIdx.x & 15, ty = threadIdx.x >> 4;
    const int tid = threadIdx.x;

    const float* Ab = A + (size_t)bh * 4096;
    #pragma unroll
    for (int i = 0; i < 16; i++) {
        int idx = tid + i * 256;
        at[idx >> 6][idx & 63] = Ab[idx];
    }
    #pragma unroll
    for (int i = 0; i < 16; i++) {
        int idx = tid + i * 256;
        wv[idx >> 6][idx & 63] = Wv[(size_t)(h * 64 + (idx >> 6)) * 256 + kq * 64 + (idx & 63)];
    }
    __syncthreads();

    float acc[4][4] = {};
    #pragma unroll
    for (int e = 0; e < 64; e++) {
        float av[4], bv[4];
        #pragma unroll
        for (int i = 0; i < 4; i++) av[i] = at[ty * 4 + i][e];
        #pragma unroll
        for (int j = 0; j < 4; j++) bv[j] = wv[e][tx * 4 + j];
        #pragma unroll
        for (int i = 0; i < 4; i++)
            #pragma unroll
            for (int j = 0; j < 4; j++)
                acc[i][j] += av[i] * bv[j];
    }
    #pragma unroll
    for (int i = 0; i < 4; i++)
        #pragma unroll
        for (int j = 0; j < 4; j++)
            U[((size_t)b * 256 + h * 64 + ty * 4 + i) * 256 + kq * 64 + tx * 4 + j] = acc[i][j];
}

// ---------------------------------------------------------------------------
// fold2: W2_b[c][k] = sum_ddg Wo[c][ddg] * U_b[ddg][k]   -> fp16
// ---------------------------------------------------------------------------
__global__ void __launch_bounds__(256) fold2_kernel(const float* __restrict__ Wo,
                                                    const float* __restrict__ U,
                                                    __half* __restrict__ W2)
{
    __shared__ float ws[16][68];
    __shared__ float us[16][68];
    const int cq = blockIdx.x, kq = blockIdx.y, b = blockIdx.z;
    const int tid = threadIdx.x;
    const int tx = tid & 15, ty = tid >> 4;
    const int lrow = tid >> 2, lk4 = (tid & 3) * 4;
    const int krow = tid >> 4, kc4 = (tid & 15) * 4;

    const float* Ub = U + ((size_t)b << 16);
    float acc[4][4] = {};

    for (int k0 = 0; k0 < 256; k0 += 16) {
        float4 wv4 = *reinterpret_cast<const float4*>(
            Wo + (size_t)(cq * 64 + lrow) * 256 + k0 + lk4);
        float4 uv4 = *reinterpret_cast<const float4*>(
            Ub + (size_t)(k0 + krow) * 256 + kq * 64 + kc4);
        __syncthreads();
        ws[lk4+0][lrow] = wv4.x; ws[lk4+1][lrow] = wv4.y;
        ws[lk4+2][lrow] = wv4.z; ws[lk4+3][lrow] = wv4.w;
        *reinterpret_cast<float4*>(&us[krow][kc4]) = uv4;
        __syncthreads();
        #pragma unroll
        for (int kk = 0; kk < 16; kk++) {
            float4 a = *reinterpret_cast<const float4*>(&ws[kk][ty * 4]);
            float4 bb = *reinterpret_cast<const float4*>(&us[kk][tx * 4]);
            float av[4] = {a.x, a.y, a.z, a.w};
            float bv[4] = {bb.x, bb.y, bb.z, bb.w};
            #pragma unroll
            for (int i = 0; i < 4; i++)
                #pragma unroll
                for (int j = 0; j < 4; j++)
                    acc[i][j] += av[i] * bv[j];
        }
    }
    #pragma unroll
    for (int i = 0; i < 4; i++)
        #pragma unroll
        for (int j = 0; j < 4; j++)
            W2[((size_t)b << 16) + (size_t)(cq * 64 + ty * 4 + i) * 256 + kq * 64 + tx * 4 + j] =
                __float2half(acc[i][j]);
}

// ---------------------------------------------------------------------------
extern "C" void kernel_launch(void* const* d_in, const int* in_sizes, int n_in,
                              void* d_out, int out_size)
{
    (void)in_sizes; (void)n_in; (void)out_size;
    const float* x1 = (const float*)d_in[0];
    const float* x2 = (const float*)d_in[1];
    const float* Wq = (const float*)d_in[2];
    const float* Wk = (const float*)d_in[3];
    const float* Wv = (const float*)d_in[4];
    const float* Wo = (const float*)d_in[5];
    const float* bo = (const float*)d_in[6];
    const float* temperature = (const float*)d_in[7];
    float* out = (float*)d_out;

    __half *qh, *kh, *wh, *w2h;
    float *u, *gp, *attn, *nssp, *nss2;
    cudaGetSymbolAddress((void**)&qh,  g_qh);
    cudaGetSymbolAddress((void**)&kh,  g_kh);
    cudaGetSymbolAddress((void**)&wh,  g_wh);
    cudaGetSymbolAddress((void**)&w2h, g_w2h);
    cudaGetSymbolAddress((void**)&u,   g_u);
    cudaGetSymbolAddress((void**)&gp,  g_gp);
    cudaGetSymbolAddress((void**)&attn, g_attn);
    cudaGetSymbolAddress((void**)&nssp, g_nssp);
    cudaGetSymbolAddress((void**)&nss2, g_nss2);

    cudaFuncSetAttribute(gemm_h<false>, cudaFuncAttributeMaxDynamicSharedMemorySize, SMEM_T);
    cudaFuncSetAttribute(gemm_h<true >, cudaFuncAttributeMaxDynamicSharedMemorySize, SMEM_T);
    cudaFuncSetAttribute(gram_mma, cudaFuncAttributeMaxDynamicSharedMemorySize, GSMEM);

    cvt_w_kernel<<<dim3(64, 2), 256>>>((const float4*)Wq, (const float4*)Wk, wh);

    gemm_h<false><<<dim3(NCTA, 1, 2), 512, SMEM_T>>>(
        x1, wh, qh, x2, wh + Cn * Cn, kh, nullptr, nullptr, nssp);

    reduce_nss<<<dim3(Bn, 2), 256>>>(nssp, nss2);
    gram_mma<<<dim3(BHn, GSP), 256, GSMEM>>>(qh, kh, gp);
    softmax_kernel<<<BHn * Dn, 64>>>(gp, nss2, temperature, attn);

    fold1_kernel<<<dim3(BHn, 4), 256>>>(attn, Wv, u);
    fold2_kernel<<<dim3(4, 4, Bn), 256>>>(Wo, u, w2h);

    gemm_h<true><<<dim3(NCTA, 1, 1), 512, SMEM_T>>>(
        x2, w2h, nullptr, nullptr, nullptr, nullptr, bo, out, nullptr);
}

// round 12
// speedup vs baseline: 1.0780x; 1.0351x over previous
#include <cuda_runtime.h>
#include <cuda_fp16.h>
#include <math.h>
#include <stdint.h>

#define Bn 8
#define Nn 8192
#define Cn 256
#define Hn 4
#define Dn 64
#define BHn (Bn*Hn)
#define MTOT (Bn*Nn)
#define GSP 16
#define GSL (Nn/GSP)
#define NCTA (MTOT/128)   // 512

// ---------------------------------------------------------------------------
// Scratch (__device__ globals; no allocation allowed)
// ---------------------------------------------------------------------------
__device__ __half g_qh [MTOT*Cn];
__device__ __half g_kh [MTOT*Cn];
__device__ __half g_wh [2*Cn*Cn];
__device__ __half g_w2h[Bn*Cn*Cn];
__device__ float  g_u  [Bn*Cn*Cn];
__device__ float  g_gp [BHn*GSP*Dn*Dn];
__device__ float  g_attn[BHn*Dn*Dn];
__device__ float  g_nssp[2*NCTA*Cn];
__device__ float  g_nss2[2*Bn*Cn];

// ---------------------------------------------------------------------------
// Helpers
// ---------------------------------------------------------------------------
__device__ __forceinline__ uint32_t smem_u32(const void* p) {
    uint32_t a;
    asm("{ .reg .u64 t; cvta.to.shared.u64 t, %1; cvt.u32.u64 %0, t; }" : "=r"(a) : "l"(p));
    return a;
}
__device__ __forceinline__ void cp16(uint32_t sdst, const void* gsrc) {
    asm volatile("cp.async.cg.shared.global [%0], [%1], 16;"
                 :: "r"(sdst), "l"(__cvta_generic_to_global(gsrc)) : "memory");
}
#define CP_COMMIT() asm volatile("cp.async.commit_group;" ::: "memory")
#define CP_WAIT1()  asm volatile("cp.async.wait_group 1;" ::: "memory")
#define CP_WAIT2()  asm volatile("cp.async.wait_group 2;" ::: "memory")

#define LDSM4(r0, r1, r2, r3, addr) \
    asm volatile("ldmatrix.sync.aligned.m8n8.x4.shared.b16 {%0,%1,%2,%3}, [%4];" \
                 : "=r"(r0), "=r"(r1), "=r"(r2), "=r"(r3) : "r"(addr))
#define LDSM4T(r0, r1, r2, r3, addr) \
    asm volatile("ldmatrix.sync.aligned.m8n8.x4.trans.shared.b16 {%0,%1,%2,%3}, [%4];" \
                 : "=r"(r0), "=r"(r1), "=r"(r2), "=r"(r3) : "r"(addr))
#define LDSM2T(r0, r1, addr) \
    asm volatile("ldmatrix.sync.aligned.m8n8.x2.trans.shared.b16 {%0,%1}, [%2];" \
                 : "=r"(r0), "=r"(r1) : "r"(addr))

__device__ __forceinline__ void mma_f16(float* d, const uint32_t* a, const uint32_t* b) {
    asm volatile(
        "mma.sync.aligned.m16n8k16.row.col.f32.f16.f16.f32 "
        "{%0,%1,%2,%3}, {%4,%5,%6,%7}, {%8,%9}, {%0,%1,%2,%3};"
        : "+f"(d[0]), "+f"(d[1]), "+f"(d[2]), "+f"(d[3])
        : "r"(a[0]), "r"(a[1]), "r"(a[2]), "r"(a[3]), "r"(b[0]), "r"(b[1]));
}

// ---------------------------------------------------------------------------
// fp16 mma GEMM, fp32 A converted in-flight, CTA 128x256, 512 threads,
// warps 4Mx4N (32x64 each). K=256 in 4 chunks of 64, 3-stage pipeline.
// Round-9 ordering: MMA block first, then stA4 + loadB + commit.
// ---------------------------------------------------------------------------
#define RSH 72
#define A_STG (128*RSH*2)               // 18432 B
#define B_STG (256*RSH*2)               // 36864 B
#define NST 3
#define SMEM_T (NST*(A_STG+B_STG) + 4096)

template<bool OUTF32>
__global__ void __launch_bounds__(512, 1) gemm_h(const float* __restrict__ X0,
                                                 const __half* __restrict__ W0,
                                                 __half* __restrict__ Yh0,
                                                 const float* __restrict__ X1,
                                                 const __half* __restrict__ W1,
                                                 __half* __restrict__ Yh1,
                                                 const float* __restrict__ bias,
                                                 float* __restrict__ Yf,
                                                 float* __restrict__ nssp)
{
    extern __shared__ char sm[];
    const uint32_t sA = smem_u32(sm);
    const uint32_t sB = sA + NST * A_STG;
    float* part = reinterpret_cast<float*>(sm + NST * (A_STG + B_STG));

    const int tid  = threadIdx.x;
    const int wid  = tid >> 5, lane = tid & 31;
    const int wm   = wid & 3;
    const int wn   = wid >> 2;
    const int gid  = lane >> 2;
    const int tig  = lane & 3;
    const int m0   = blockIdx.x * 128;
    const int z    = OUTF32 ? 0 : blockIdx.z;

    const float* X = (!OUTF32 && z) ? X1 : X0;
    const __half* Wp = OUTF32 ? W0 + ((size_t)(m0 >> 13) << 16) : (z ? W1 : W0);
    __half* Yh = z ? Yh1 : Yh0;

    const int lrA = ((lane >> 3) & 1) * 8 + (lane & 7);
    const int lkA = (lane >> 4) * 8;
    const int lrB = (lane >> 4) * 8 + (lane & 7);
    const int lkB = ((lane >> 3) & 1) * 8;
    int aoffs[2], boffs[4];
    #pragma unroll
    for (int mt = 0; mt < 2; mt++) aoffs[mt] = (wm * 32 + mt * 16 + lrA) * RSH + lkA;
    #pragma unroll
    for (int nb = 0; nb < 4; nb++) boffs[nb] = (wn * 64 + nb * 16 + lrB) * RSH + lkB;

    auto ldA4 = [&](int k0, float4* p) {
        #pragma unroll
        for (int i = 0; i < 4; i++) {
            int g = tid + i * 512;
            p[i] = *reinterpret_cast<const float4*>(
                X + (size_t)(m0 + (g >> 4)) * Cn + k0 + (g & 15) * 4);
        }
    };
    auto stA4 = [&](int st, const float4* p) {
        #pragma unroll
        for (int i = 0; i < 4; i++) {
            int g = tid + i * 512;
            __half2 h0 = __floats2half2_rn(p[i].x, p[i].y);
            __half2 h1 = __floats2half2_rn(p[i].z, p[i].w);
            uint2 u;
            u.x = *reinterpret_cast<uint32_t*>(&h0);
            u.y = *reinterpret_cast<uint32_t*>(&h1);
            *reinterpret_cast<uint2*>(sm + st * A_STG + ((g >> 4) * RSH + (g & 15) * 4) * 2) = u;
        }
    };
    auto loadB = [&](int st, int k0) {
        #pragma unroll
        for (int i = 0; i < 4; i++) {
            int g = tid + i * 512;
            int r = g >> 3, kq = g & 7;
            cp16(sB + st * B_STG + (r * RSH + kq * 8) * 2,
                 Wp + (size_t)r * Cn + k0 + kq * 8);
        }
    };

    float acc[2][8][4] = {};

    {   // prologue: stages 0,1
        float4 p0[4], p1[4];
        ldA4(0, p0); ldA4(64, p1);
        stA4(0, p0); loadB(0, 0);  CP_COMMIT();
        stA4(1, p1); loadB(1, 64); CP_COMMIT();
    }

    for (int ch = 0; ch < 4; ch++) {
        float4 pn[4];
        if (ch + 2 < 4) ldA4((ch + 2) * 64, pn);
        CP_WAIT1();
        __syncthreads();

        const int st = ch % 3;
        const uint32_t a0 = sA + st * A_STG;
        const uint32_t b0a = sB + st * B_STG;

        #pragma unroll
        for (int ks = 0; ks < 4; ks++) {
            uint32_t af[2][4];
            #pragma unroll
            for (int mt = 0; mt < 2; mt++)
                LDSM4(af[mt][0], af[mt][1], af[mt][2], af[mt][3],
                      a0 + (aoffs[mt] + ks * 16) * 2);
            uint32_t bf[8][2];
            #pragma unroll
            for (int nb = 0; nb < 4; nb++) {
                uint32_t r0, r1, r2, r3;
                LDSM4(r0, r1, r2, r3, b0a + (boffs[nb] + ks * 16) * 2);
                bf[nb * 2][0] = r0; bf[nb * 2][1] = r1;
                bf[nb * 2 + 1][0] = r2; bf[nb * 2 + 1][1] = r3;
            }
            #pragma unroll
            for (int mt = 0; mt < 2; mt++)
                #pragma unroll
                for (int nt = 0; nt < 8; nt++)
                    mma_f16(acc[mt][nt], af[mt], bf[nt]);
        }

        if (ch + 2 < 4) {
            stA4((ch + 2) % 3, pn);
            loadB((ch + 2) % 3, (ch + 2) * 64);
        }
        CP_COMMIT();
    }

    // Output
    #pragma unroll
    for (int mt = 0; mt < 2; mt++) {
        const int m = m0 + wm * 32 + mt * 16 + gid;
        #pragma unroll
        for (int nt = 0; nt < 8; nt++) {
            const int cg = wn * 64 + nt * 8 + tig * 2;
            if (OUTF32) {
                float b0 = __ldg(bias + cg), b1 = __ldg(bias + cg + 1);
                float2 v0 = make_float2(acc[mt][nt][0] + b0, acc[mt][nt][1] + b1);
                float2 v1 = make_float2(acc[mt][nt][2] + b0, acc[mt][nt][3] + b1);
                *reinterpret_cast<float2*>(Yf + (size_t)m * Cn + cg)       = v0;
                *reinterpret_cast<float2*>(Yf + (size_t)(m + 8) * Cn + cg) = v1;
            } else {
                __half2 h0 = __floats2half2_rn(acc[mt][nt][0], acc[mt][nt][1]);
                __half2 h1 = __floats2half2_rn(acc[mt][nt][2], acc[mt][nt][3]);
                *reinterpret_cast<__half2*>(Yh + (size_t)m * Cn + cg)       = h0;
                *reinterpret_cast<__half2*>(Yh + (size_t)(m + 8) * Cn + cg) = h1;
            }
        }
    }

    if (!OUTF32) {
        float cs[8][2];
        #pragma unroll
        for (int nt = 0; nt < 8; nt++) {
            cs[nt][0] = acc[0][nt][0] * acc[0][nt][0] + acc[0][nt][2] * acc[0][nt][2]
                      + acc[1][nt][0] * acc[1][nt][0] + acc[1][nt][2] * acc[1][nt][2];
            cs[nt][1] = acc[0][nt][1] * acc[0][nt][1] + acc[0][nt][3] * acc[0][nt][3]
                      + acc[1][nt][1] * acc[1][nt][1] + acc[1][nt][3] * acc[1][nt][3];
        }
        #pragma unroll
        for (int nt = 0; nt < 8; nt++)
            #pragma unroll
            for (int j = 0; j < 2; j++) {
                cs[nt][j] += __shfl_xor_sync(0xffffffffu, cs[nt][j], 4);
                cs[nt][j] += __shfl_xor_sync(0xffffffffu, cs[nt][j], 8);
                cs[nt][j] += __shfl_xor_sync(0xffffffffu, cs[nt][j], 16);
            }
        if (gid == 0) {
            #pragma unroll
            for (int nt = 0; nt < 8; nt++) {
                part[wm * 256 + wn * 64 + nt * 8 + tig * 2]     = cs[nt][0];
                part[wm * 256 + wn * 64 + nt * 8 + tig * 2 + 1] = cs[nt][1];
            }
        }
        __syncthreads();
        if (tid < 256) {
            float s = part[tid] + part[256 + tid] + part[512 + tid] + part[768 + tid];
            nssp[((size_t)z * NCTA + blockIdx.x) * 256 + tid] = s;
        }
    }
}

// ---------------------------------------------------------------------------
// Reduce per-CTA sumsq partials -> per-batch norms (deterministic order)
// ---------------------------------------------------------------------------
__global__ void __launch_bounds__(256) reduce_nss(const float* __restrict__ nssp,
                                                  float* __restrict__ nss2)
{
    const int b = blockIdx.x, z = blockIdx.y, c = threadIdx.x;
    float s = 0.f;
    #pragma unroll 8
    for (int i = 0; i < 64; i++)
        s += nssp[((size_t)z * NCTA + b * 64 + i) * 256 + c];
    nss2[(z * Bn + b) * 256 + c] = s;
}

// ---------------------------------------------------------------------------
// Gram via fp16 mma with ldmatrix.trans — 4-stage cp.async, single barrier
// ---------------------------------------------------------------------------
#define GRS 72
#define GSTG (64*GRS*2)          // 9216 B per operand per stage
#define GSMEM (8*GSTG)           // 73728 B

__global__ void __launch_bounds__(256) gram_mma(const __half* __restrict__ Qh,
                                                const __half* __restrict__ Kh,
                                                float* __restrict__ Gp)
{
    extern __shared__ char smg[];
    const uint32_t sq = smem_u32(smg);
    const uint32_t sk = sq + 4 * GSTG;

    const int bh = blockIdx.x, sp = blockIdx.y;
    const int b = bh >> 2, h = bh & 3;
    const int tid = threadIdx.x;
    const int w = tid >> 5, lane = tid & 31;
    const int gid = lane >> 2, tig = lane & 3;
    const int t0 = sp * GSL;

    const __half* qb = Qh + ((size_t)b * Nn) * 256 + h * 64;
    const __half* kb = Kh + ((size_t)b * Nn) * 256 + h * 64;

    auto gload = [&](int st, int tc) {
        #pragma unroll
        for (int i = 0; i < 2; i++) {
            int g = tid + i * 256;
            int r = g >> 3, ck = g & 7;
            cp16(sq + st * GSTG + (r * GRS + ck * 8) * 2,
                 qb + (size_t)(t0 + tc + r) * 256 + ck * 8);
        }
        #pragma unroll
        for (int i = 0; i < 2; i++) {
            int g = tid + i * 256;
            int r = g >> 3, ck = g & 7;
            cp16(sk + st * GSTG + (r * GRS + ck * 8) * 2,
                 kb + (size_t)(t0 + tc + r) * 256 + ck * 8);
        }
    };

    const int aH = (((lane >> 4) & 1) * 8 + (lane & 7)) * GRS + ((lane >> 3) & 1) * 8;
    const int bH = (((lane >> 3) & 1) * 8 + (lane & 7)) * GRS + w * 8;

    float acc[4][4] = {};

    gload(0, 0);   CP_COMMIT();
    gload(1, 64);  CP_COMMIT();
    gload(2, 128); CP_COMMIT();

    const int NCH = GSL / 64;   // 8
    for (int c = 0; c < NCH; c++) {
        CP_WAIT2();
        __syncthreads();
        if (c + 3 < NCH) gload((c + 3) & 3, (c + 3) * 64);
        CP_COMMIT();

        const uint32_t aq = sq + (c & 3) * GSTG;
        const uint32_t ak = sk + (c & 3) * GSTG;

        #pragma unroll
        for (int st16 = 0; st16 < 4; st16++) {
            const int kb16 = st16 * 16;
            uint32_t bfr[2];
            LDSM2T(bfr[0], bfr[1], ak + (kb16 * GRS + bH) * 2);
            #pragma unroll
            for (int mt = 0; mt < 4; mt++) {
                uint32_t af[4];
                LDSM4T(af[0], af[1], af[2], af[3],
                       aq + (kb16 * GRS + aH + mt * 16) * 2);
                mma_f16(acc[mt], af, bfr);
            }
        }
    }

    float* g = Gp + (((size_t)bh * GSP + sp) << 12);
    #pragma unroll
    for (int mt = 0; mt < 4; mt++) {
        const int r0 = mt * 16 + gid;
        *reinterpret_cast<float2*>(g + r0 * 64 + w * 8 + tig * 2) =
            make_float2(acc[mt][0], acc[mt][1]);
        *reinterpret_cast<float2*>(g + (r0 + 8) * 64 + w * 8 + tig * 2) =
            make_float2(acc[mt][2], acc[mt][3]);
    }
}

// ---------------------------------------------------------------------------
// Weight f32 -> f16
// ---------------------------------------------------------------------------
__device__ __forceinline__ void cvt_store4(__half* dst, float4 v) {
    __half2 h0 = __floats2half2_rn(v.x, v.y);
    __half2 h1 = __floats2half2_rn(v.z, v.w);
    uint2 u;
    u.x = *reinterpret_cast<uint32_t*>(&h0);
    u.y = *reinterpret_cast<uint32_t*>(&h1);
    *reinterpret_cast<uint2*>(dst) = u;
}

__global__ void __launch_bounds__(256) cvt_w_kernel(const float4* __restrict__ wq,
                                                    const float4* __restrict__ wk,
                                                    __half* dst)
{
    const int n4 = (Cn * Cn) / 4;
    const float4* src = blockIdx.y == 0 ? wq : wk;
    __half* d = dst + (size_t)blockIdx.y * Cn * Cn;
    int i = blockIdx.x * 256 + threadIdx.x;
    if (i < n4) cvt_store4(d + i * 4, src[i]);
}

// ---------------------------------------------------------------------------
// Reduce gram partials, normalize * temperature, softmax
// ---------------------------------------------------------------------------
__global__ void __launch_bounds__(64) softmax_kernel(const float* __restrict__ Gp,
                                                     const float* __restrict__ nss2,
                                                     const float* __restrict__ temp,
                                                     float* __restrict__ A)
{
    const int r  = blockIdx.x;
    const int bh = r >> 6;
    const int dd = r & 63;
    const int b  = bh >> 2, h = bh & 3;
    const int e  = threadIdx.x;

    const float rq = 1.0f / fmaxf(sqrtf(nss2[(0 * Bn + b) * 256 + h * 64 + dd]), 1e-12f);
    const float rk = 1.0f / fmaxf(sqrtf(nss2[(1 * Bn + b) * 256 + h * 64 + e]), 1e-12f);

    float s = 0.f;
    #pragma unroll
    for (int sp = 0; sp < GSP; sp++)
        s += Gp[(((size_t)bh * GSP + sp) << 12) + dd * 64 + e];
    s *= rq * rk * temp[h];

    __shared__ float red[64];
    red[e] = s;
    __syncthreads();
    for (int st = 32; st > 0; st >>= 1) {
        if (e < st) red[e] = fmaxf(red[e], red[e + st]);
        __syncthreads();
    }
    float m = red[0];
    __syncthreads();
    float ex = __expf(s - m);
    red[e] = ex;
    __syncthreads();
    for (int st = 32; st > 0; st >>= 1) {
        if (e < st) red[e] += red[e + st];
        __syncthreads();
    }
    A[(size_t)bh * 4096 + dd * 64 + e] = ex / red[0];
}

// ---------------------------------------------------------------------------
// fold1: U_b[h*64+dd][k] = sum_e attn[bh][dd][e] * Wv[h*64+e][k]   (fp32)
// ---------------------------------------------------------------------------
__global__ void __launch_bounds__(256) fold1_kernel(const float* __restrict__ A,
                                                    const float* __restrict__ Wv,
                                                    float* __restrict__ U)
{
    __shared__ float at[64][65];
    __shared__ float wv[64][65];
    const int bh = blockIdx.x, kq = blockIdx.y;
    const int b = bh >> 2, h = bh & 3;
    const int tx = threadIdx.x & 15, ty = threadIdx.x >> 4;
    const int tid = threadIdx.x;

    const float* Ab = A + (size_t)bh * 4096;
    #pragma unroll
    for (int i = 0; i < 16; i++) {
        int idx = tid + i * 256;
        at[idx >> 6][idx & 63] = Ab[idx];
    }
    #pragma unroll
    for (int i = 0; i < 16; i++) {
        int idx = tid + i * 256;
        wv[idx >> 6][idx & 63] = Wv[(size_t)(h * 64 + (idx >> 6)) * 256 + kq * 64 + (idx & 63)];
    }
    __syncthreads();

    float acc[4][4] = {};
    #pragma unroll
    for (int e = 0; e < 64; e++) {
        float av[4], bv[4];
        #pragma unroll
        for (int i = 0; i < 4; i++) av[i] = at[ty * 4 + i][e];
        #pragma unroll
        for (int j = 0; j < 4; j++) bv[j] = wv[e][tx * 4 + j];
        #pragma unroll
        for (int i = 0; i < 4; i++)
            #pragma unroll
            for (int j = 0; j < 4; j++)
                acc[i][j] += av[i] * bv[j];
    }
    #pragma unroll
    for (int i = 0; i < 4; i++)
        #pragma unroll
        for (int j = 0; j < 4; j++)
            U[((size_t)b * 256 + h * 64 + ty * 4 + i) * 256 + kq * 64 + tx * 4 + j] = acc[i][j];
}

// ---------------------------------------------------------------------------
// fold2: W2_b[c][k] = sum_ddg Wo[c][ddg] * U_b[ddg][k]   -> fp16
// ---------------------------------------------------------------------------
__global__ void __launch_bounds__(256) fold2_kernel(const float* __restrict__ Wo,
                                                    const float* __restrict__ U,
                                                    __half* __restrict__ W2)
{
    __shared__ float ws[16][68];
    __shared__ float us[16][68];
    const int cq = blockIdx.x, kq = blockIdx.y, b = blockIdx.z;
    const int tid = threadIdx.x;
    const int tx = tid & 15, ty = tid >> 4;
    const int lrow = tid >> 2, lk4 = (tid & 3) * 4;
    const int krow = tid >> 4, kc4 = (tid & 15) * 4;

    const float* Ub = U + ((size_t)b << 16);
    float acc[4][4] = {};

    for (int k0 = 0; k0 < 256; k0 += 16) {
        float4 wv4 = *reinterpret_cast<const float4*>(
            Wo + (size_t)(cq * 64 + lrow) * 256 + k0 + lk4);
        float4 uv4 = *reinterpret_cast<const float4*>(
            Ub + (size_t)(k0 + krow) * 256 + kq * 64 + kc4);
        __syncthreads();
        ws[lk4+0][lrow] = wv4.x; ws[lk4+1][lrow] = wv4.y;
        ws[lk4+2][lrow] = wv4.z; ws[lk4+3][lrow] = wv4.w;
        *reinterpret_cast<float4*>(&us[krow][kc4]) = uv4;
        __syncthreads();
        #pragma unroll
        for (int kk = 0; kk < 16; kk++) {
            float4 a = *reinterpret_cast<const float4*>(&ws[kk][ty * 4]);
            float4 bb = *reinterpret_cast<const float4*>(&us[kk][tx * 4]);
            float av[4] = {a.x, a.y, a.z, a.w};
            float bv[4] = {bb.x, bb.y, bb.z, bb.w};
            #pragma unroll
            for (int i = 0; i < 4; i++)
                #pragma unroll
                for (int j = 0; j < 4; j++)
                    acc[i][j] += av[i] * bv[j];
        }
    }
    #pragma unroll
    for (int i = 0; i < 4; i++)
        #pragma unroll
        for (int j = 0; j < 4; j++)
            W2[((size_t)b << 16) + (size_t)(cq * 64 + ty * 4 + i) * 256 + kq * 64 + tx * 4 + j] =
                __float2half(acc[i][j]);
}

// ---------------------------------------------------------------------------
extern "C" void kernel_launch(void* const* d_in, const int* in_sizes, int n_in,
                              void* d_out, int out_size)
{
    (void)in_sizes; (void)n_in; (void)out_size;
    const float* x1 = (const float*)d_in[0];
    const float* x2 = (const float*)d_in[1];
    const float* Wq = (const float*)d_in[2];
    const float* Wk = (const float*)d_in[3];
    const float* Wv = (const float*)d_in[4];
    const float* Wo = (const float*)d_in[5];
    const float* bo = (const float*)d_in[6];
    const float* temperature = (const float*)d_in[7];
    float* out = (float*)d_out;

    __half *qh, *kh, *wh, *w2h;
    float *u, *gp, *attn, *nssp, *nss2;
    cudaGetSymbolAddress((void**)&qh,  g_qh);
    cudaGetSymbolAddress((void**)&kh,  g_kh);
    cudaGetSymbolAddress((void**)&wh,  g_wh);
    cudaGetSymbolAddress((void**)&w2h, g_w2h);
    cudaGetSymbolAddress((void**)&u,   g_u);
    cudaGetSymbolAddress((void**)&gp,  g_gp);
    cudaGetSymbolAddress((void**)&attn, g_attn);
    cudaGetSymbolAddress((void**)&nssp, g_nssp);
    cudaGetSymbolAddress((void**)&nss2, g_nss2);

    cudaFuncSetAttribute(gemm_h<false>, cudaFuncAttributeMaxDynamicSharedMemorySize, SMEM_T);
    cudaFuncSetAttribute(gemm_h<true >, cudaFuncAttributeMaxDynamicSharedMemorySize, SMEM_T);
    cudaFuncSetAttribute(gram_mma, cudaFuncAttributeMaxDynamicSharedMemorySize, GSMEM);

    cvt_w_kernel<<<dim3(64, 2), 256>>>((const float4*)Wq, (const float4*)Wk, wh);

    gemm_h<false><<<dim3(NCTA, 1, 2), 512, SMEM_T>>>(
        x1, wh, qh, x2, wh + Cn * Cn, kh, nullptr, nullptr, nssp);

    reduce_nss<<<dim3(Bn, 2), 256>>>(nssp, nss2);
    gram_mma<<<dim3(BHn, GSP), 256, GSMEM>>>(qh, kh, gp);
    softmax_kernel<<<BHn * Dn, 64>>>(gp, nss2, temperature, attn);

    fold1_kernel<<<dim3(BHn, 4), 256>>>(attn, Wv, u);
    fold2_kernel<<<dim3(4, 4, Bn), 256>>>(Wo, u, w2h);

    gemm_h<true><<<dim3(NCTA, 1, 1), 512, SMEM_T>>>(
        x2, w2h, nullptr, nullptr, nullptr, nullptr, bo, out, nullptr);
}

// round 13
// speedup vs baseline: 1.0820x; 1.0038x over previous
#include <cuda_runtime.h>
#include <cuda_fp16.h>
#include <math.h>
#include <stdint.h>

#define Bn 8
#define Nn 8192
#define Cn 256
#define Hn 4
#define Dn 64
#define BHn (Bn*Hn)
#define MTOT (Bn*Nn)
#define GSP 8
#define GSL (Nn/GSP)      // 1024
#define NCTA (MTOT/128)   // 512

// ---------------------------------------------------------------------------
// Scratch (__device__ globals; no allocation allowed)
// ---------------------------------------------------------------------------
__device__ __half g_qh [MTOT*Cn];
__device__ __half g_kh [MTOT*Cn];
__device__ __half g_wh [2*Cn*Cn];
__device__ __half g_w2h[Bn*Cn*Cn];
__device__ float  g_u  [Bn*Cn*Cn];
__device__ float  g_gp [BHn*GSP*Dn*Dn];
__device__ float  g_attn[BHn*Dn*Dn];
__device__ float  g_nssp[2*NCTA*Cn];
__device__ float  g_nss2[2*Bn*Cn];

// ---------------------------------------------------------------------------
// Helpers
// ---------------------------------------------------------------------------
__device__ __forceinline__ uint32_t smem_u32(const void* p) {
    uint32_t a;
    asm("{ .reg .u64 t; cvta.to.shared.u64 t, %1; cvt.u32.u64 %0, t; }" : "=r"(a) : "l"(p));
    return a;
}
__device__ __forceinline__ void cp16(uint32_t sdst, const void* gsrc) {
    asm volatile("cp.async.cg.shared.global [%0], [%1], 16;"
                 :: "r"(sdst), "l"(__cvta_generic_to_global(gsrc)) : "memory");
}
#define CP_COMMIT() asm volatile("cp.async.commit_group;" ::: "memory")
#define CP_WAIT1()  asm volatile("cp.async.wait_group 1;" ::: "memory")
#define CP_WAIT2()  asm volatile("cp.async.wait_group 2;" ::: "memory")

#define LDSM4(r0, r1, r2, r3, addr) \
    asm volatile("ldmatrix.sync.aligned.m8n8.x4.shared.b16 {%0,%1,%2,%3}, [%4];" \
                 : "=r"(r0), "=r"(r1), "=r"(r2), "=r"(r3) : "r"(addr))
#define LDSM4T(r0, r1, r2, r3, addr) \
    asm volatile("ldmatrix.sync.aligned.m8n8.x4.trans.shared.b16 {%0,%1,%2,%3}, [%4];" \
                 : "=r"(r0), "=r"(r1), "=r"(r2), "=r"(r3) : "r"(addr))
#define LDSM2T(r0, r1, addr) \
    asm volatile("ldmatrix.sync.aligned.m8n8.x2.trans.shared.b16 {%0,%1}, [%2];" \
                 : "=r"(r0), "=r"(r1) : "r"(addr))

__device__ __forceinline__ void mma_f16(float* d, const uint32_t* a, const uint32_t* b) {
    asm volatile(
        "mma.sync.aligned.m16n8k16.row.col.f32.f16.f16.f32 "
        "{%0,%1,%2,%3}, {%4,%5,%6,%7}, {%8,%9}, {%0,%1,%2,%3};"
        : "+f"(d[0]), "+f"(d[1]), "+f"(d[2]), "+f"(d[3])
        : "r"(a[0]), "r"(a[1]), "r"(a[2]), "r"(a[3]), "r"(b[0]), "r"(b[1]));
}

// ---------------------------------------------------------------------------
// fp16 mma GEMM, fp32 A converted in-flight, CTA 128x256, 512 threads,
// warps 4Mx4N (32x64 each). K=256 in 4 chunks of 64, 3-stage pipeline.
// Round-9 ordering: MMA block first, then stA4 + loadB + commit.
// ---------------------------------------------------------------------------
#define RSH 72
#define A_STG (128*RSH*2)               // 18432 B
#define B_STG (256*RSH*2)               // 36864 B
#define NST 3
#define SMEM_T (NST*(A_STG+B_STG) + 4096)

template<bool OUTF32>
__global__ void __launch_bounds__(512, 1) gemm_h(const float* __restrict__ X0,
                                                 const __half* __restrict__ W0,
                                                 __half* __restrict__ Yh0,
                                                 const float* __restrict__ X1,
                                                 const __half* __restrict__ W1,
                                                 __half* __restrict__ Yh1,
                                                 const float* __restrict__ bias,
                                                 float* __restrict__ Yf,
                                                 float* __restrict__ nssp)
{
    extern __shared__ char sm[];
    const uint32_t sA = smem_u32(sm);
    const uint32_t sB = sA + NST * A_STG;
    float* part = reinterpret_cast<float*>(sm + NST * (A_STG + B_STG));

    const int tid  = threadIdx.x;
    const int wid  = tid >> 5, lane = tid & 31;
    const int wm   = wid & 3;
    const int wn   = wid >> 2;
    const int gid  = lane >> 2;
    const int tig  = lane & 3;
    const int m0   = blockIdx.x * 128;
    const int z    = OUTF32 ? 0 : blockIdx.z;

    const float* X = (!OUTF32 && z) ? X1 : X0;
    const __half* Wp = OUTF32 ? W0 + ((size_t)(m0 >> 13) << 16) : (z ? W1 : W0);
    __half* Yh = z ? Yh1 : Yh0;

    const int lrA = ((lane >> 3) & 1) * 8 + (lane & 7);
    const int lkA = (lane >> 4) * 8;
    const int lrB = (lane >> 4) * 8 + (lane & 7);
    const int lkB = ((lane >> 3) & 1) * 8;
    int aoffs[2], boffs[4];
    #pragma unroll
    for (int mt = 0; mt < 2; mt++) aoffs[mt] = (wm * 32 + mt * 16 + lrA) * RSH + lkA;
    #pragma unroll
    for (int nb = 0; nb < 4; nb++) boffs[nb] = (wn * 64 + nb * 16 + lrB) * RSH + lkB;

    auto ldA4 = [&](int k0, float4* p) {
        #pragma unroll
        for (int i = 0; i < 4; i++) {
            int g = tid + i * 512;
            p[i] = *reinterpret_cast<const float4*>(
                X + (size_t)(m0 + (g >> 4)) * Cn + k0 + (g & 15) * 4);
        }
    };
    auto stA4 = [&](int st, const float4* p) {
        #pragma unroll
        for (int i = 0; i < 4; i++) {
            int g = tid + i * 512;
            __half2 h0 = __floats2half2_rn(p[i].x, p[i].y);
            __half2 h1 = __floats2half2_rn(p[i].z, p[i].w);
            uint2 u;
            u.x = *reinterpret_cast<uint32_t*>(&h0);
            u.y = *reinterpret_cast<uint32_t*>(&h1);
            *reinterpret_cast<uint2*>(sm + st * A_STG + ((g >> 4) * RSH + (g & 15) * 4) * 2) = u;
        }
    };
    auto loadB = [&](int st, int k0) {
        #pragma unroll
        for (int i = 0; i < 4; i++) {
            int g = tid + i * 512;
            int r = g >> 3, kq = g & 7;
            cp16(sB + st * B_STG + (r * RSH + kq * 8) * 2,
                 Wp + (size_t)r * Cn + k0 + kq * 8);
        }
    };

    float acc[2][8][4] = {};

    {   // prologue: stages 0,1
        float4 p0[4], p1[4];
        ldA4(0, p0); ldA4(64, p1);
        stA4(0, p0); loadB(0, 0);  CP_COMMIT();
        stA4(1, p1); loadB(1, 64); CP_COMMIT();
    }

    for (int ch = 0; ch < 4; ch++) {
        float4 pn[4];
        if (ch + 2 < 4) ldA4((ch + 2) * 64, pn);
        CP_WAIT1();
        __syncthreads();

        const int st = ch % 3;
        const uint32_t a0 = sA + st * A_STG;
        const uint32_t b0a = sB + st * B_STG;

        #pragma unroll
        for (int ks = 0; ks < 4; ks++) {
            uint32_t af[2][4];
            #pragma unroll
            for (int mt = 0; mt < 2; mt++)
                LDSM4(af[mt][0], af[mt][1], af[mt][2], af[mt][3],
                      a0 + (aoffs[mt] + ks * 16) * 2);
            uint32_t bf[8][2];
            #pragma unroll
            for (int nb = 0; nb < 4; nb++) {
                uint32_t r0, r1, r2, r3;
                LDSM4(r0, r1, r2, r3, b0a + (boffs[nb] + ks * 16) * 2);
                bf[nb * 2][0] = r0; bf[nb * 2][1] = r1;
                bf[nb * 2 + 1][0] = r2; bf[nb * 2 + 1][1] = r3;
            }
            #pragma unroll
            for (int mt = 0; mt < 2; mt++)
                #pragma unroll
                for (int nt = 0; nt < 8; nt++)
                    mma_f16(acc[mt][nt], af[mt], bf[nt]);
        }

        if (ch + 2 < 4) {
            stA4((ch + 2) % 3, pn);
            loadB((ch + 2) % 3, (ch + 2) * 64);
        }
        CP_COMMIT();
    }

    // Output
    #pragma unroll
    for (int mt = 0; mt < 2; mt++) {
        const int m = m0 + wm * 32 + mt * 16 + gid;
        #pragma unroll
        for (int nt = 0; nt < 8; nt++) {
            const int cg = wn * 64 + nt * 8 + tig * 2;
            if (OUTF32) {
                float b0 = __ldg(bias + cg), b1 = __ldg(bias + cg + 1);
                float2 v0 = make_float2(acc[mt][nt][0] + b0, acc[mt][nt][1] + b1);
                float2 v1 = make_float2(acc[mt][nt][2] + b0, acc[mt][nt][3] + b1);
                *reinterpret_cast<float2*>(Yf + (size_t)m * Cn + cg)       = v0;
                *reinterpret_cast<float2*>(Yf + (size_t)(m + 8) * Cn + cg) = v1;
            } else {
                __half2 h0 = __floats2half2_rn(acc[mt][nt][0], acc[mt][nt][1]);
                __half2 h1 = __floats2half2_rn(acc[mt][nt][2], acc[mt][nt][3]);
                *reinterpret_cast<__half2*>(Yh + (size_t)m * Cn + cg)       = h0;
                *reinterpret_cast<__half2*>(Yh + (size_t)(m + 8) * Cn + cg) = h1;
            }
        }
    }

    if (!OUTF32) {
        float cs[8][2];
        #pragma unroll
        for (int nt = 0; nt < 8; nt++) {
            cs[nt][0] = acc[0][nt][0] * acc[0][nt][0] + acc[0][nt][2] * acc[0][nt][2]
                      + acc[1][nt][0] * acc[1][nt][0] + acc[1][nt][2] * acc[1][nt][2];
            cs[nt][1] = acc[0][nt][1] * acc[0][nt][1] + acc[0][nt][3] * acc[0][nt][3]
                      + acc[1][nt][1] * acc[1][nt][1] + acc[1][nt][3] * acc[1][nt][3];
        }
        #pragma unroll
        for (int nt = 0; nt < 8; nt++)
            #pragma unroll
            for (int j = 0; j < 2; j++) {
                cs[nt][j] += __shfl_xor_sync(0xffffffffu, cs[nt][j], 4);
                cs[nt][j] += __shfl_xor_sync(0xffffffffu, cs[nt][j], 8);
                cs[nt][j] += __shfl_xor_sync(0xffffffffu, cs[nt][j], 16);
            }
        if (gid == 0) {
            #pragma unroll
            for (int nt = 0; nt < 8; nt++) {
                part[wm * 256 + wn * 64 + nt * 8 + tig * 2]     = cs[nt][0];
                part[wm * 256 + wn * 64 + nt * 8 + tig * 2 + 1] = cs[nt][1];
            }
        }
        __syncthreads();
        if (tid < 256) {
            float s = part[tid] + part[256 + tid] + part[512 + tid] + part[768 + tid];
            nssp[((size_t)z * NCTA + blockIdx.x) * 256 + tid] = s;
        }
    }
}

// ---------------------------------------------------------------------------
// Reduce per-CTA sumsq partials -> per-batch norms (deterministic order)
// ---------------------------------------------------------------------------
__global__ void __launch_bounds__(256) reduce_nss(const float* __restrict__ nssp,
                                                  float* __restrict__ nss2)
{
    const int b = blockIdx.x, z = blockIdx.y, c = threadIdx.x;
    float s = 0.f;
    #pragma unroll 8
    for (int i = 0; i < 64; i++)
        s += nssp[((size_t)z * NCTA + b * 64 + i) * 256 + c];
    nss2[(z * Bn + b) * 256 + c] = s;
}

// ---------------------------------------------------------------------------
// Gram via fp16 mma with ldmatrix.trans — 4-stage cp.async, single barrier,
// GSP=8 -> 256 CTAs (single wave), 16 chunks per CTA.
// ---------------------------------------------------------------------------
#define GRS 72
#define GSTG (64*GRS*2)          // 9216 B per operand per stage
#define GSMEM (8*GSTG)           // 73728 B

__global__ void __launch_bounds__(256) gram_mma(const __half* __restrict__ Qh,
                                                const __half* __restrict__ Kh,
                                                float* __restrict__ Gp)
{
    extern __shared__ char smg[];
    const uint32_t sq = smem_u32(smg);
    const uint32_t sk = sq + 4 * GSTG;

    const int bh = blockIdx.x, sp = blockIdx.y;
    const int b = bh >> 2, h = bh & 3;
    const int tid = threadIdx.x;
    const int w = tid >> 5, lane = tid & 31;
    const int gid = lane >> 2, tig = lane & 3;
    const int t0 = sp * GSL;

    const __half* qb = Qh + ((size_t)b * Nn) * 256 + h * 64;
    const __half* kb = Kh + ((size_t)b * Nn) * 256 + h * 64;

    auto gload = [&](int st, int tc) {
        #pragma unroll
        for (int i = 0; i < 2; i++) {
            int g = tid + i * 256;
            int r = g >> 3, ck = g & 7;
            cp16(sq + st * GSTG + (r * GRS + ck * 8) * 2,
                 qb + (size_t)(t0 + tc + r) * 256 + ck * 8);
        }
        #pragma unroll
        for (int i = 0; i < 2; i++) {
            int g = tid + i * 256;
            int r = g >> 3, ck = g & 7;
            cp16(sk + st * GSTG + (r * GRS + ck * 8) * 2,
                 kb + (size_t)(t0 + tc + r) * 256 + ck * 8);
        }
    };

    const int aH = (((lane >> 4) & 1) * 8 + (lane & 7)) * GRS + ((lane >> 3) & 1) * 8;
    const int bH = (((lane >> 3) & 1) * 8 + (lane & 7)) * GRS + w * 8;

    float acc[4][4] = {};

    gload(0, 0);   CP_COMMIT();
    gload(1, 64);  CP_COMMIT();
    gload(2, 128); CP_COMMIT();

    const int NCH = GSL / 64;   // 16
    for (int c = 0; c < NCH; c++) {
        CP_WAIT2();
        __syncthreads();
        if (c + 3 < NCH) gload((c + 3) & 3, (c + 3) * 64);
        CP_COMMIT();

        const uint32_t aq = sq + (c & 3) * GSTG;
        const uint32_t ak = sk + (c & 3) * GSTG;

        #pragma unroll
        for (int st16 = 0; st16 < 4; st16++) {
            const int kb16 = st16 * 16;
            uint32_t bfr[2];
            LDSM2T(bfr[0], bfr[1], ak + (kb16 * GRS + bH) * 2);
            #pragma unroll
            for (int mt = 0; mt < 4; mt++) {
                uint32_t af[4];
                LDSM4T(af[0], af[1], af[2], af[3],
                       aq + (kb16 * GRS + aH + mt * 16) * 2);
                mma_f16(acc[mt], af, bfr);
            }
        }
    }

    float* g = Gp + (((size_t)bh * GSP + sp) << 12);
    #pragma unroll
    for (int mt = 0; mt < 4; mt++) {
        const int r0 = mt * 16 + gid;
        *reinterpret_cast<float2*>(g + r0 * 64 + w * 8 + tig * 2) =
            make_float2(acc[mt][0], acc[mt][1]);
        *reinterpret_cast<float2*>(g + (r0 + 8) * 64 + w * 8 + tig * 2) =
            make_float2(acc[mt][2], acc[mt][3]);
    }
}

// ---------------------------------------------------------------------------
// Weight f32 -> f16
// ---------------------------------------------------------------------------
__device__ __forceinline__ void cvt_store4(__half* dst, float4 v) {
    __half2 h0 = __floats2half2_rn(v.x, v.y);
    __half2 h1 = __floats2half2_rn(v.z, v.w);
    uint2 u;
    u.x = *reinterpret_cast<uint32_t*>(&h0);
    u.y = *reinterpret_cast<uint32_t*>(&h1);
    *reinterpret_cast<uint2*>(dst) = u;
}

__global__ void __launch_bounds__(256) cvt_w_kernel(const float4* __restrict__ wq,
                                                    const float4* __restrict__ wk,
                                                    __half* dst)
{
    const int n4 = (Cn * Cn) / 4;
    const float4* src = blockIdx.y == 0 ? wq : wk;
    __half* d = dst + (size_t)blockIdx.y * Cn * Cn;
    int i = blockIdx.x * 256 + threadIdx.x;
    if (i < n4) cvt_store4(d + i * 4, src[i]);
}

// ---------------------------------------------------------------------------
// Reduce gram partials, normalize * temperature, softmax
// ---------------------------------------------------------------------------
__global__ void __launch_bounds__(64) softmax_kernel(const float* __restrict__ Gp,
                                                     const float* __restrict__ nss2,
                                                     const float* __restrict__ temp,
                                                     float* __restrict__ A)
{
    const int r  = blockIdx.x;
    const int bh = r >> 6;
    const int dd = r & 63;
    const int b  = bh >> 2, h = bh & 3;
    const int e  = threadIdx.x;

    const float rq = 1.0f / fmaxf(sqrtf(nss2[(0 * Bn + b) * 256 + h * 64 + dd]), 1e-12f);
    const float rk = 1.0f / fmaxf(sqrtf(nss2[(1 * Bn + b) * 256 + h * 64 + e]), 1e-12f);

    float s = 0.f;
    #pragma unroll
    for (int sp = 0; sp < GSP; sp++)
        s += Gp[(((size_t)bh * GSP + sp) << 12) + dd * 64 + e];
    s *= rq * rk * temp[h];

    __shared__ float red[64];
    red[e] = s;
    __syncthreads();
    for (int st = 32; st > 0; st >>= 1) {
        if (e < st) red[e] = fmaxf(red[e], red[e + st]);
        __syncthreads();
    }
    float m = red[0];
    __syncthreads();
    float ex = __expf(s - m);
    red[e] = ex;
    __syncthreads();
    for (int st = 32; st > 0; st >>= 1) {
        if (e < st) red[e] += red[e + st];
        __syncthreads();
    }
    A[(size_t)bh * 4096 + dd * 64 + e] = ex / red[0];
}

// ---------------------------------------------------------------------------
// fold1: U_b[h*64+dd][k] = sum_e attn[bh][dd][e] * Wv[h*64+e][k]   (fp32)
// ---------------------------------------------------------------------------
__global__ void __launch_bounds__(256) fold1_kernel(const float* __restrict__ A,
                                                    const float* __restrict__ Wv,
                                                    float* __restrict__ U)
{
    __shared__ float at[64][65];
    __shared__ float wv[64][65];
    const int bh = blockIdx.x, kq = blockIdx.y;
    const int b = bh >> 2, h = bh & 3;
    const int tx = threadIdx.x & 15, ty = threadIdx.x >> 4;
    const int tid = threadIdx.x;

    const float* Ab = A + (size_t)bh * 4096;
    #pragma unroll
    for (int i = 0; i < 16; i++) {
        int idx = tid + i * 256;
        at[idx >> 6][idx & 63] = Ab[idx];
    }
    #pragma unroll
    for (int i = 0; i < 16; i++) {
        int idx = tid + i * 256;
        wv[idx >> 6][idx & 63] = Wv[(size_t)(h * 64 + (idx >> 6)) * 256 + kq * 64 + (idx & 63)];
    }
    __syncthreads();

    float acc[4][4] = {};
    #pragma unroll
    for (int e = 0; e < 64; e++) {
        float av[4], bv[4];
        #pragma unroll
        for (int i = 0; i < 4; i++) av[i] = at[ty * 4 + i][e];
        #pragma unroll
        for (int j = 0; j < 4; j++) bv[j] = wv[e][tx * 4 + j];
        #pragma unroll
        for (int i = 0; i < 4; i++)
            #pragma unroll
            for (int j = 0; j < 4; j++)
                acc[i][j] += av[i] * bv[j];
    }
    #pragma unroll
    for (int i = 0; i < 4; i++)
        #pragma unroll
        for (int j = 0; j < 4; j++)
            U[((size_t)b * 256 + h * 64 + ty * 4 + i) * 256 + kq * 64 + tx * 4 + j] = acc[i][j];
}

// ---------------------------------------------------------------------------
// fold2: W2_b[c][k] = sum_ddg Wo[c][ddg] * U_b[ddg][k]   -> fp16
// ---------------------------------------------------------------------------
__global__ void __launch_bounds__(256) fold2_kernel(const float* __restrict__ Wo,
                                                    const float* __restrict__ U,
                                                    __half* __restrict__ W2)
{
    __shared__ float ws[16][68];
    __shared__ float us[16][68];
    const int cq = blockIdx.x, kq = blockIdx.y, b = blockIdx.z;
    const int tid = threadIdx.x;
    const int tx = tid & 15, ty = tid >> 4;
    const int lrow = tid >> 2, lk4 = (tid & 3) * 4;
    const int krow = tid >> 4, kc4 = (tid & 15) * 4;

    const float* Ub = U + ((size_t)b << 16);
    float acc[4][4] = {};

    for (int k0 = 0; k0 < 256; k0 += 16) {
        float4 wv4 = *reinterpret_cast<const float4*>(
            Wo + (size_t)(cq * 64 + lrow) * 256 + k0 + lk4);
        float4 uv4 = *reinterpret_cast<const float4*>(
            Ub + (size_t)(k0 + krow) * 256 + kq * 64 + kc4);
        __syncthreads();
        ws[lk4+0][lrow] = wv4.x; ws[lk4+1][lrow] = wv4.y;
        ws[lk4+2][lrow] = wv4.z; ws[lk4+3][lrow] = wv4.w;
        *reinterpret_cast<float4*>(&us[krow][kc4]) = uv4;
        __syncthreads();
        #pragma unroll
        for (int kk = 0; kk < 16; kk++) {
            float4 a = *reinterpret_cast<const float4*>(&ws[kk][ty * 4]);
            float4 bb = *reinterpret_cast<const float4*>(&us[kk][tx * 4]);
            float av[4] = {a.x, a.y, a.z, a.w};
            float bv[4] = {bb.x, bb.y, bb.z, bb.w};
            #pragma unroll
            for (int i = 0; i < 4; i++)
                #pragma unroll
                for (int j = 0; j < 4; j++)
                    acc[i][j] += av[i] * bv[j];
        }
    }
    #pragma unroll
    for (int i = 0; i < 4; i++)
        #pragma unroll
        for (int j = 0; j < 4; j++)
            W2[((size_t)b << 16) + (size_t)(cq * 64 + ty * 4 + i) * 256 + kq * 64 + tx * 4 + j] =
                __float2half(acc[i][j]);
}

// ---------------------------------------------------------------------------
extern "C" void kernel_launch(void* const* d_in, const int* in_sizes, int n_in,
                              void* d_out, int out_size)
{
    (void)in_sizes; (void)n_in; (void)out_size;
    const float* x1 = (const float*)d_in[0];
    const float* x2 = (const float*)d_in[1];
    const float* Wq = (const float*)d_in[2];
    const float* Wk = (const float*)d_in[3];
    const float* Wv = (const float*)d_in[4];
    const float* Wo = (const float*)d_in[5];
    const float* bo = (const float*)d_in[6];
    const float* temperature = (const float*)d_in[7];
    float* out = (float*)d_out;

    __half *qh, *kh, *wh, *w2h;
    float *u, *gp, *attn, *nssp, *nss2;
    cudaGetSymbolAddress((void**)&qh,  g_qh);
    cudaGetSymbolAddress((void**)&kh,  g_kh);
    cudaGetSymbolAddress((void**)&wh,  g_wh);
    cudaGetSymbolAddress((void**)&w2h, g_w2h);
    cudaGetSymbolAddress((void**)&u,   g_u);
    cudaGetSymbolAddress((void**)&gp,  g_gp);
    cudaGetSymbolAddress((void**)&attn, g_attn);
    cudaGetSymbolAddress((void**)&nssp, g_nssp);
    cudaGetSymbolAddress((void**)&nss2, g_nss2);

    cudaFuncSetAttribute(gemm_h<false>, cudaFuncAttributeMaxDynamicSharedMemorySize, SMEM_T);
    cudaFuncSetAttribute(gemm_h<true >, cudaFuncAttributeMaxDynamicSharedMemorySize, SMEM_T);
    cudaFuncSetAttribute(gram_mma, cudaFuncAttributeMaxDynamicSharedMemorySize, GSMEM);

    cvt_w_kernel<<<dim3(64, 2), 256>>>((const float4*)Wq, (const float4*)Wk, wh);

    gemm_h<false><<<dim3(NCTA, 1, 2), 512, SMEM_T>>>(
        x1, wh, qh, x2, wh + Cn * Cn, kh, nullptr, nullptr, nssp);

    reduce_nss<<<dim3(Bn, 2), 256>>>(nssp, nss2);
    gram_mma<<<dim3(BHn, GSP), 256, GSMEM>>>(qh, kh, gp);
    softmax_kernel<<<BHn * Dn, 64>>>(gp, nss2, temperature, attn);

    fold1_kernel<<<dim3(BHn, 4), 256>>>(attn, Wv, u);
    fold2_kernel<<<dim3(4, 4, Bn), 256>>>(Wo, u, w2h);

    gemm_h<true><<<dim3(NCTA, 1, 1), 512, SMEM_T>>>(
        x2, w2h, nullptr, nullptr, nullptr, nullptr, bo, out, nullptr);
}